// round 11
// baseline (speedup 1.0000x reference)
#include <cuda_runtime.h>
#include <math.h>

#define BB 16
#define HH 512
#define WW 512
#define HWL (HH*WW)
#define NTOT (BB*HWL)
#define NCAND 4096
#define NTOP 500
#define NTILE 4096   // 16 imgs * 16*16 dense tiles

// ------------- device scratch (no allocations) -------------
__device__ float  g_cval[BB*NCAND];
__device__ int    g_cidx[BB*NCAND];
__device__ double g_pA[NTILE];
__device__ double g_pB[NTILE];
__device__ double g_accS;

// gaussian(7, sigma=1) weights as literals (FFMA-imm)
#define W0 0.004433048f
#define W1 0.054005582f
#define W2 0.242036223f
#define W3 0.399050277f

__constant__ float GW[7] = {W0, W1, W2, W3, W2, W1, W0};

__device__ __forceinline__ int refl(int t, int n) {   // reflect101
    if (t < 0) t = -t;
    if (t >= n) t = 2 * n - 2 - t;
    return t;
}

// =====================================================================
// Kernel 1: fused gray->sobel->gauss7(structure tensor)->GFTT->NMS->
//           per-8x8-block argmax.  32x32 tile, 256 threads.
// smem overlays (floats), total 8064 = 31.5 KB -> 7 blocks/SM:
//   D0=0(1764) D1=1764(1764)            [42x42 dx, dy]
//   GR=3528(1936)                        [44x44] (dead after sobel)
//   B0=3528 B1=5040 B2=6552 ..8064      [42x36] (overlay GR)
//   SS=0(1296)                           [36x36] (overlay D0; D dead)
//   RM=1296(1152)                        [36x32] (overlay D)
// INTERIOR: tile touches no border -> no refl/clamp/bounds anywhere.
// =====================================================================
template<bool INT>
__device__ __forceinline__ void gftt_tile(const float* __restrict__ img,
                                          int b, int i0, int j0,
                                          int cby, int cbx, float* sm) {
    float* D0 = sm;
    float* D1 = sm + 1764;
    float* GR = sm + 3528;
    float* B0 = sm + 3528;
    float* B1 = sm + 5040;
    float* B2 = sm + 6552;
    float* SS = sm;
    float* RM = sm + 1296;

    int t  = threadIdx.x;
    int tx = t & 31, tw = t >> 5;

    // --- gray: 44 x 44 ---
    for (int r = tw; r < 44; r += 8) {
        int gi = INT ? (i0 - 6 + r) : min(max(i0 - 6 + r, 0), HH - 1);
        {
            int c = tx;
            int gj = INT ? (j0 - 6 + c) : min(max(j0 - 6 + c, 0), WW - 1);
            int p = gi * WW + gj;
            GR[r*44 + c] = 0.299f*img[p] + 0.587f*img[HWL+p] + 0.114f*img[2*HWL+p];
        }
        if (tx < 12) {
            int c = tx + 32;
            int gj = INT ? (j0 - 6 + c) : min(max(j0 - 6 + c, 0), WW - 1);
            int p = gi * WW + gj;
            GR[r*44 + c] = 0.299f*img[p] + 0.587f*img[HWL+p] + 0.114f*img[2*HWL+p];
        }
    }
    __syncthreads();

    // --- sobel dx,dy: 42 x 42 ---
    for (int r = tw; r < 42; r += 8) {
        int rm_, r0_, rp_;
        if (INT) { rm_ = r; r0_ = r + 1; rp_ = r + 2; }
        else {
            int rg = refl(i0 - 5 + r, HH);
            rm_ = max(rg - 1, 0) - (i0 - 6);
            r0_ = rg - (i0 - 6);
            rp_ = min(rg + 1, HH - 1) - (i0 - 6);
        }
#pragma unroll
        for (int m = 0; m < 2; m++) {
            int c = tx + 32 * m;
            if (c < 42) {
                int cm_, c0_, cp_;
                if (INT) { cm_ = c; c0_ = c + 1; cp_ = c + 2; }
                else {
                    int cg = refl(j0 - 5 + c, WW);
                    cm_ = max(cg - 1, 0) - (j0 - 6);
                    c0_ = cg - (j0 - 6);
                    cp_ = min(cg + 1, WW - 1) - (j0 - 6);
                }
                float A = GR[rm_*44+cm_], Bv = GR[rm_*44+c0_], C = GR[rm_*44+cp_];
                float D = GR[r0_*44+cm_],                      F = GR[r0_*44+cp_];
                float G = GR[rp_*44+cm_], H  = GR[rp_*44+c0_], K = GR[rp_*44+cp_];
                int o = r * 42 + c;
                D0[o] = (C - A + 2.f*(F - D) + K - G) * 0.125f;
                D1[o] = (G - A + 2.f*(H - Bv) + K - C) * 0.125f;
            }
        }
    }
    __syncthreads();

    // --- horizontal gauss7 on products (formed on the fly): 42 x 36 ---
    for (int r = tw; r < 42; r += 8) {
#pragma unroll
        for (int m = 0; m < 2; m++) {
            int c = tx + 32 * m;
            if (c < 36) {
                int base = r * 42 + c;
                float s0, s1, s2;
                {
                    float dx = D0[base], dy = D1[base];
                    s0 = W0 * (dx*dx); s1 = W0 * (dy*dy); s2 = W0 * (dx*dy);
                }
#define HTAP(Q, WQ) { float dx = D0[base+Q], dy = D1[base+Q]; \
                      s0 += WQ * (dx*dx); s1 += WQ * (dy*dy); s2 += WQ * (dx*dy); }
                HTAP(1, W1) HTAP(2, W2) HTAP(3, W3) HTAP(4, W2) HTAP(5, W1) HTAP(6, W0)
#undef HTAP
                int o = r * 36 + c;
                B0[o] = s0; B1[o] = s1; B2[o] = s2;
            }
        }
    }
    __syncthreads();

    // --- vertical gauss7 + GFTT response + fused NMS row-max: 36 rows ---
    for (int r = tw; r < 36; r += 8) {
        int gi = i0 - 2 + r;
        float v1 = -INFINITY, v2 = -INFINITY;
#pragma unroll
        for (int m = 0; m < 2; m++) {
            int c = tx + 32 * m;
            if (m == 0 || tx < 4) {
                float a, cc, e;
                {
                    int row = r * 36 + c;
                    a = W0 * B0[row]; cc = W0 * B1[row]; e = W0 * B2[row];
                }
#define VTAP(Q, WQ) { int row = (r+Q) * 36 + c; \
                      a += WQ * B0[row]; cc += WQ * B1[row]; e += WQ * B2[row]; }
                VTAP(1, W1) VTAP(2, W2) VTAP(3, W3) VTAP(4, W2) VTAP(5, W1) VTAP(6, W0)
#undef VTAP
                float det = a * cc - e * e, tr = a + cc;
                float s = 0.5f * (tr - sqrtf(fabsf(tr * tr - 4.f * det)));
                if (!INT) {
                    int gj = j0 - 2 + c;
                    s = (gi >= 0 && gi < HH && gj >= 0 && gj < WW) ? s : -INFINITY;
                }
                SS[r * 36 + c] = s;
                if (m == 0) v1 = s; else v2 = s;
            }
        }
        // row-max over window [tx, tx+4] via shuffles (cols 32..35 live in v2 of lanes 0..3)
        float rm = v1;
#pragma unroll
        for (int off = 1; off <= 4; off++) {
            float x = __shfl_down_sync(0xffffffffu, v1, off);
            float y = __shfl_sync(0xffffffffu, v2, (tx + off) & 31);
            rm = fmaxf(rm, (tx + off < 32) ? x : y);
        }
        RM[r * 32 + tx] = rm;
    }
    __syncthreads();

    // --- per-pixel NMS + 8x8 block argmax: warp tw handles blocks 2tw, 2tw+1 ---
#pragma unroll
    for (int k = 0; k < 2; k++) {
        int bb = 2 * tw + k;
        int br = bb >> 2, bc = bb & 3;
        float bv = -1.f; int bi = 0x7fffffff;
#pragma unroll
        for (int h = 0; h < 2; h++) {
            int e = tx + 32 * h;
            int r = br * 8 + (e >> 3), c = bc * 8 + (e & 7);
            float s = SS[(r + 2) * 36 + c + 2];
            float mx = RM[r * 32 + c];
#pragma unroll
            for (int q = 1; q < 5; q++) mx = fmaxf(mx, RM[(r + q) * 32 + c]);
            float v = (s == mx) ? s : 0.f;
            int gix = (i0 + r) * WW + (j0 + c);
            if (v > bv || (v == bv && gix < bi)) { bv = v; bi = gix; }
        }
#pragma unroll
        for (int off = 16; off >= 1; off >>= 1) {
            float ov = __shfl_down_sync(0xffffffffu, bv, off);
            int   oi = __shfl_down_sync(0xffffffffu, bi, off);
            if (ov > bv || (ov == bv && oi < bi)) { bv = ov; bi = oi; }
        }
        if (tx == 0) {
            int cy = cby * 4 + br;
            int cx = cbx * 4 + bc;
            g_cval[b * NCAND + cy * 64 + cx] = bv;
            g_cidx[b * NCAND + cy * 64 + cx] = bi;
        }
    }
}

__global__ void __launch_bounds__(256) k_gftt(const float* __restrict__ imgs) {
    __shared__ float sm[8064];
    int b  = blockIdx.z;
    int i0 = blockIdx.y * 32, j0 = blockIdx.x * 32;
    if (b == 0 && blockIdx.x == 0 && blockIdx.y == 0 && threadIdx.x == 0)
        g_accS = 0.0;
    const float* img = imgs + (size_t)b * 3 * HWL;
    bool interior = (blockIdx.y >= 1 && blockIdx.y <= 14 &&
                     blockIdx.x >= 1 && blockIdx.x <= 14);
    if (interior) gftt_tile<true >(img, b, i0, j0, blockIdx.y, blockIdx.x, sm);
    else          gftt_tile<false>(img, b, i0, j0, blockIdx.y, blockIdx.x, sm);
}

// =====================================================================
// Kernel 2: per-image top-500 (radix select) + sparse corner-BCE fused.
// Points kept in shared memory; sparse phase: warp-per-point.
// =====================================================================
__global__ void __launch_bounds__(512) k_topk_sparse(const float* __restrict__ sc) {
    int b = blockIdx.x;
    const float* cv = g_cval + b * NCAND;
    const int*   ci = g_cidx + b * NCAND;
    __shared__ unsigned hist[256];
    __shared__ unsigned scan[256];
    __shared__ unsigned sh_prefix, sh_k, sh_cnt, sh_eqcnt;
    __shared__ int sh_npt;
    __shared__ int eqidx[256];
    __shared__ int sh_pts[NTOP];

    unsigned u[8];
#pragma unroll
    for (int i = 0; i < 8; i++) {
        unsigned bits = __float_as_uint(cv[threadIdx.x + i * 512]);
        u[i] = bits ^ ((bits & 0x80000000u) ? 0xFFFFFFFFu : 0x80000000u);
    }
    if (threadIdx.x == 0) { sh_prefix = 0; sh_k = NTOP; sh_cnt = 0; sh_eqcnt = 0; }

    for (int shift = 24; shift >= 0; shift -= 8) {
        if (threadIdx.x < 256) hist[threadIdx.x] = 0;
        __syncthreads();
        unsigned pre = sh_prefix;
#pragma unroll
        for (int i = 0; i < 8; i++) {
            if (((unsigned long long)u[i] >> (shift + 8)) == (unsigned long long)pre)
                atomicAdd(&hist[(u[i] >> shift) & 255u], 1u);
        }
        __syncthreads();
        if (threadIdx.x < 256) scan[threadIdx.x] = hist[threadIdx.x];
        __syncthreads();
        for (int off = 1; off < 256; off <<= 1) {
            unsigned add = 0;
            if (threadIdx.x < 256 && threadIdx.x + off < 256)
                add = scan[threadIdx.x + off];
            __syncthreads();
            if (threadIdx.x < 256) scan[threadIdx.x] += add;
            __syncthreads();
        }
        if (threadIdx.x < 256) {
            unsigned k = sh_k;
            unsigned Sq  = scan[threadIdx.x];
            unsigned Sq1 = (threadIdx.x == 255) ? 0u : scan[threadIdx.x + 1];
            if (Sq >= k && Sq1 < k) {
                sh_k = k - Sq1;
                sh_prefix = (pre << 8) | (unsigned)threadIdx.x;
            }
        }
        __syncthreads();
    }

    unsigned uth = sh_prefix;
    int kneed = (int)sh_k;
    float thresh = (uth & 0x80000000u) ? __uint_as_float(uth ^ 0x80000000u)
                                       : __uint_as_float(~uth);

    if (thresh > 0.f) {
#pragma unroll
        for (int i = 0; i < 8; i++) {
            int idx = threadIdx.x + i * 512;
            if (u[i] > uth) {
                unsigned p = atomicAdd(&sh_cnt, 1u);
                if (p < NTOP) sh_pts[p] = ci[idx];
            } else if (u[i] == uth) {
                unsigned p = atomicAdd(&sh_eqcnt, 1u);
                if (p < 256) eqidx[p] = ci[idx];
            }
        }
        __syncthreads();
        if (threadIdx.x == 0) {
            int base = min((int)sh_cnt, NTOP);
            int nn = min((int)sh_eqcnt, 256);
            int added = 0;
            while (added < kneed && added < nn) {
                int best = -1, bi2 = 0x7fffffff;
                for (int q = 0; q < nn; q++)
                    if (eqidx[q] >= 0 && eqidx[q] < bi2) { bi2 = eqidx[q]; best = q; }
                if (best < 0) break;
                if (base + added < NTOP) sh_pts[base + added] = bi2;
                eqidx[best] = -1;
                added++;
            }
            sh_npt = min(base + added, NTOP);
        }
    } else {
#pragma unroll
        for (int i = 0; i < 8; i++) {
            int idx = threadIdx.x + i * 512;
            if (u[i] > 0x80000000u) {               // ordered form of +0.0
                unsigned p = atomicAdd(&sh_cnt, 1u);
                if (p < NTOP) sh_pts[p] = ci[idx];
            }
        }
        __syncthreads();
        if (threadIdx.x == 0) sh_npt = min((int)sh_cnt, NTOP);
    }
    __syncthreads();

    // ---- sparse phase: warp-per-point over sh_pts ----
    int n = sh_npt;
    const float* P = sc + (size_t)b * HWL;
    int lane = threadIdx.x & 31, wid = threadIdx.x >> 5;
    double acc = 0.0;
    for (int q = wid; q < n; q += 16) {
        int pix = sh_pts[q];
        int pi = pix >> 9, pj = pix & 511;
#pragma unroll
        for (int half = 0; half < 2; half++) {
            int tap = lane + 32 * half;
            if (tap >= 49) break;
            int kr = tap / 7, kc = tap - kr * 7;
            int R = pi - 3 + kr, C = pj - 3 + kc;
            if (R < 0 || R >= HH || C < 0 || C >= WW) continue;
            float wrow = GW[kr];
            if (pi >= 1 && pi <= 3) {
                int d = -pi - R;
                if (d >= -3 && d <= 3) wrow += GW[d+3];
            }
            if (pi >= HH-4 && pi <= HH-2) {
                int d = 2*HH - 2 - pi - R;
                if (d >= -3 && d <= 3) wrow += GW[d+3];
            }
            float wcol = GW[kc];
            if (pj >= 1 && pj <= 3) {
                int d = -pj - C;
                if (d >= -3 && d <= 3) wcol += GW[d+3];
            }
            if (pj >= WW-4 && pj <= WW-2) {
                int d = 2*WW - 2 - pj - C;
                if (d >= -3 && d <= 3) wcol += GW[d+3];
            }
            float pv = P[R*WW + C];
            float lg = fmaxf(logf(pv), -100.f);
            float l1 = fmaxf(log1pf(-pv), -100.f);
            acc += (double)((wrow * wcol) * (l1 - lg));
        }
    }
    __shared__ double wsum[16];
    for (int off = 16; off; off >>= 1) acc += __shfl_down_sync(0xffffffffu, acc, off);
    if (lane == 0) wsum[wid] = acc;
    __syncthreads();
    if (threadIdx.x == 0) {
        double s2 = 0;
        for (int k = 0; k < 16; k++) s2 += wsum[k];
        atomicAdd(&g_accS, s2);
    }
}

// =====================================================================
// Kernel 3: dense part — sum(-log1mp) and reg = p*exp(-lap), tiled 32x32
// =====================================================================
__global__ void __launch_bounds__(1024) k_dense(const float* __restrict__ sc) {
    __shared__ float s[36*36];
    __shared__ float h[36*32];
    __shared__ double w1[32], w2[32];
    int b = blockIdx.z, i0 = blockIdx.y * 32, j0 = blockIdx.x * 32;
    int tx = threadIdx.x, ty = threadIdx.y, t = ty*32 + tx;
    const float* P = sc + (size_t)b * HWL;
    for (int idx = t; idx < 36*36; idx += 1024) {
        int a = idx / 36, c = idx % 36;
        s[idx] = P[refl(i0 - 2 + a, HH) * WW + refl(j0 - 2 + c, WW)];
    }
    __syncthreads();
    for (int idx = t; idx < 36*32; idx += 1024) {
        int r = idx / 32, c = idx % 32;
        float x = s[r*36 + c];
#pragma unroll
        for (int k = 1; k < 5; k++) x += s[r*36 + c + k];
        h[idx] = x;
    }
    __syncthreads();
    float p = s[(ty+2)*36 + tx + 2];
    float box = h[ty*32 + tx];
#pragma unroll
    for (int k = 1; k < 5; k++) box += h[(ty+k)*32 + tx];
    float lap = (box - 25.f * p) * (1.f / 48.f);
    double reg = (double)(p * expf(-lap));
    double bce = (double)(-fmaxf(log1pf(-p), -100.f));
    for (int off = 16; off; off >>= 1) {
        bce += __shfl_down_sync(0xffffffffu, bce, off);
        reg += __shfl_down_sync(0xffffffffu, reg, off);
    }
    if ((t & 31) == 0) { w1[t >> 5] = bce; w2[t >> 5] = reg; }
    __syncthreads();
    if (t < 32) {
        bce = w1[t]; reg = w2[t];
        for (int off = 16; off; off >>= 1) {
            bce += __shfl_down_sync(0xffffffffu, bce, off);
            reg += __shfl_down_sync(0xffffffffu, reg, off);
        }
        if (t == 0) {
            int tile = (b * 16 + blockIdx.y) * 16 + blockIdx.x;
            g_pA[tile] = bce; g_pB[tile] = reg;
        }
    }
}

// =====================================================================
// Kernel 4: final reduce
// =====================================================================
__global__ void k_fin(float* __restrict__ out) {
    double a = 0, r = 0;
    for (int i = threadIdx.x; i < NTILE; i += blockDim.x) { a += g_pA[i]; r += g_pB[i]; }
    __shared__ double sa[256], sr[256];
    sa[threadIdx.x] = a; sr[threadIdx.x] = r;
    __syncthreads();
    for (int off = 128; off; off >>= 1) {
        if (threadIdx.x < off) { sa[threadIdx.x] += sa[threadIdx.x+off]; sr[threadIdx.x] += sr[threadIdx.x+off]; }
        __syncthreads();
    }
    if (threadIdx.x == 0)
        out[0] = (float)(((sa[0] + g_accS) + 10.0 * sr[0]) / (double)NTOT);
}

// ---------------- streams/events for fork-join overlap ----------------
struct HxStreams {
    cudaStream_t side;
    cudaEvent_t evFork, evJoin;
    HxStreams() {
        cudaStreamCreateWithFlags(&side, cudaStreamNonBlocking);
        cudaEventCreateWithFlags(&evFork, cudaEventDisableTiming);
        cudaEventCreateWithFlags(&evJoin, cudaEventDisableTiming);
    }
};
static HxStreams g_hx;

// =====================================================================
extern "C" void kernel_launch(void* const* d_in, const int* in_sizes, int n_in,
                              void* d_out, int out_size) {
    const float* scores = (const float*)d_in[0];
    const float* imgs   = (const float*)d_in[1];
    if (n_in >= 2 && in_sizes[0] > in_sizes[1]) {
        scores = (const float*)d_in[1];
        imgs   = (const float*)d_in[0];
    }
    float* out = (float*)d_out;

    // fork: dense pass runs concurrently with gftt->topk/sparse chain
    cudaEventRecord(g_hx.evFork, 0);
    cudaStreamWaitEvent(g_hx.side, g_hx.evFork, 0);
    k_dense<<<dim3(16, 16, BB), dim3(32, 32), 0, g_hx.side>>>(scores);
    cudaEventRecord(g_hx.evJoin, g_hx.side);

    k_gftt<<<dim3(16, 16, BB), 256>>>(imgs);
    k_topk_sparse<<<BB, 512>>>(scores);

    // join
    cudaStreamWaitEvent(0, g_hx.evJoin, 0);
    k_fin<<<1, 256>>>(out);
    (void)out_size;
}

// round 12
// speedup vs baseline: 1.1521x; 1.1521x over previous
#include <cuda_runtime.h>
#include <math.h>

#define BB 16
#define HH 512
#define WW 512
#define HWL (HH*WW)
#define NTOT (BB*HWL)
#define NCAND 4096
#define NTOP 500
#define NTILE 4096   // 16 imgs * 16*16 dense tiles

// ------------- device scratch (no allocations) -------------
__device__ float  g_cval[BB*NCAND];
__device__ int    g_cidx[BB*NCAND];
__device__ int    g_pts[BB*NTOP];
__device__ int    g_npt[BB];
__device__ double g_pA[NTILE];
__device__ double g_pB[NTILE];
__device__ double g_accS;

// gaussian(7, sigma=1) weights as literals (FFMA-imm)
#define W0 0.004433048f
#define W1 0.054005582f
#define W2 0.242036223f
#define W3 0.399050277f

__constant__ float GW[7] = {W0, W1, W2, W3, W2, W1, W0};

__device__ __forceinline__ int refl(int t, int n) {   // reflect101
    if (t < 0) t = -t;
    if (t >= n) t = 2 * n - 2 - t;
    return t;
}

// =====================================================================
// Kernel 1: fused gray->sobel->gauss7(structure tensor)->GFTT->NMS->
//           per-8x8-block argmax.  32x32 tile, 256 threads.
// smem overlays (floats), total 8064 = 31.5 KB -> 7 blocks/SM:
//   D0=0(1764) D1=1764(1764)            [42x42 dx, dy]
//   GR=3528(1936)                        [44x44] (dead after sobel)
//   B0=3528 B1=5040 B2=6552 ..8064      [42x36] (overlay GR)
//   SS=0(1296)                           [36x36] (overlay D0; D dead)
//   RM=1296(1152)                        [36x32] (overlay D)
// =====================================================================
__global__ void __launch_bounds__(256) k_gftt(const float* __restrict__ imgs) {
    __shared__ float sm[8064];
    float* D0 = sm;
    float* D1 = sm + 1764;
    float* GR = sm + 3528;
    float* B0 = sm + 3528;
    float* B1 = sm + 5040;
    float* B2 = sm + 6552;
    float* SS = sm;
    float* RM = sm + 1296;

    int b  = blockIdx.z;
    int i0 = blockIdx.y * 32, j0 = blockIdx.x * 32;
    int t  = threadIdx.x;
    int tx = t & 31, tw = t >> 5;
    if (b == 0 && blockIdx.x == 0 && blockIdx.y == 0 && t == 0) g_accS = 0.0;

    const float* img = imgs + (size_t)b * 3 * HWL;

    // --- gray: 44 x 44 (clamped coords) ---
    for (int r = tw; r < 44; r += 8) {
        int gi = min(max(i0 - 6 + r, 0), HH - 1);
        {
            int c = tx;
            int gj = min(max(j0 - 6 + c, 0), WW - 1);
            int p = gi * WW + gj;
            GR[r*44 + c] = 0.299f*img[p] + 0.587f*img[HWL+p] + 0.114f*img[2*HWL+p];
        }
        if (tx < 12) {
            int c = tx + 32;
            int gj = min(max(j0 - 6 + c, 0), WW - 1);
            int p = gi * WW + gj;
            GR[r*44 + c] = 0.299f*img[p] + 0.587f*img[HWL+p] + 0.114f*img[2*HWL+p];
        }
    }
    __syncthreads();

    // --- sobel dx,dy: 42 x 42 at reflected coords ---
    for (int r = tw; r < 42; r += 8) {
        int rg = refl(i0 - 5 + r, HH);
        int rm_ = max(rg - 1, 0) - (i0 - 6);
        int r0_ = rg - (i0 - 6);
        int rp_ = min(rg + 1, HH - 1) - (i0 - 6);
#pragma unroll
        for (int m = 0; m < 2; m++) {
            int c = tx + 32 * m;
            if (c < 42) {
                int cg = refl(j0 - 5 + c, WW);
                int cm_ = max(cg - 1, 0) - (j0 - 6);
                int c0_ = cg - (j0 - 6);
                int cp_ = min(cg + 1, WW - 1) - (j0 - 6);
                float A = GR[rm_*44+cm_], Bv = GR[rm_*44+c0_], C = GR[rm_*44+cp_];
                float D = GR[r0_*44+cm_],                      F = GR[r0_*44+cp_];
                float G = GR[rp_*44+cm_], H  = GR[rp_*44+c0_], K = GR[rp_*44+cp_];
                int o = r * 42 + c;
                D0[o] = (C - A + 2.f*(F - D) + K - G) * 0.125f;
                D1[o] = (G - A + 2.f*(H - Bv) + K - C) * 0.125f;
            }
        }
    }
    __syncthreads();

    // --- horizontal gauss7 on products (formed on the fly): 42 x 36 ---
    for (int r = tw; r < 42; r += 8) {
#pragma unroll
        for (int m = 0; m < 2; m++) {
            int c = tx + 32 * m;
            if (c < 36) {
                int base = r * 42 + c;
                float s0, s1, s2;
                {
                    float dx = D0[base], dy = D1[base];
                    s0 = W0 * (dx*dx); s1 = W0 * (dy*dy); s2 = W0 * (dx*dy);
                }
#define HTAP(Q, WQ) { float dx = D0[base+Q], dy = D1[base+Q]; \
                      s0 += WQ * (dx*dx); s1 += WQ * (dy*dy); s2 += WQ * (dx*dy); }
                HTAP(1, W1) HTAP(2, W2) HTAP(3, W3) HTAP(4, W2) HTAP(5, W1) HTAP(6, W0)
#undef HTAP
                int o = r * 36 + c;
                B0[o] = s0; B1[o] = s1; B2[o] = s2;
            }
        }
    }
    __syncthreads();

    // --- vertical gauss7 + GFTT response: 36 x 36 ---
    for (int r = tw; r < 36; r += 8) {
        int gi = i0 - 2 + r;
#pragma unroll
        for (int m = 0; m < 2; m++) {
            int c = tx + 32 * m;
            if (c < 36) {
                float a, cc, e;
                {
                    int row = r * 36 + c;
                    a = W0 * B0[row]; cc = W0 * B1[row]; e = W0 * B2[row];
                }
#define VTAP(Q, WQ) { int row = (r+Q) * 36 + c; \
                      a += WQ * B0[row]; cc += WQ * B1[row]; e += WQ * B2[row]; }
                VTAP(1, W1) VTAP(2, W2) VTAP(3, W3) VTAP(4, W2) VTAP(5, W1) VTAP(6, W0)
#undef VTAP
                int gj = j0 - 2 + c;
                float det = a * cc - e * e, tr = a + cc;
                float s = 0.5f * (tr - sqrtf(fabsf(tr * tr - 4.f * det)));
                SS[r * 36 + c] = (gi >= 0 && gi < HH && gj >= 0 && gj < WW)
                               ? s : -INFINITY;
            }
        }
    }
    __syncthreads();

    // --- NMS row-max: 36 x 32 ---
    for (int r = tw; r < 36; r += 8) {
        float mx = SS[r * 36 + tx];
#pragma unroll
        for (int q = 1; q < 5; q++) mx = fmaxf(mx, SS[r * 36 + tx + q]);
        RM[r * 32 + tx] = mx;
    }
    __syncthreads();

    // --- per-pixel NMS + 8x8 block argmax: warp tw handles blocks 2tw, 2tw+1 ---
#pragma unroll
    for (int k = 0; k < 2; k++) {
        int bb = 2 * tw + k;
        int br = bb >> 2, bc = bb & 3;
        float bv = -1.f; int bi = 0x7fffffff;
#pragma unroll
        for (int h = 0; h < 2; h++) {
            int e = tx + 32 * h;
            int r = br * 8 + (e >> 3), c = bc * 8 + (e & 7);
            float s = SS[(r + 2) * 36 + c + 2];
            float mx = RM[r * 32 + c];
#pragma unroll
            for (int q = 1; q < 5; q++) mx = fmaxf(mx, RM[(r + q) * 32 + c]);
            float v = (s == mx) ? s : 0.f;
            int gix = (i0 + r) * WW + (j0 + c);
            if (v > bv || (v == bv && gix < bi)) { bv = v; bi = gix; }
        }
#pragma unroll
        for (int off = 16; off >= 1; off >>= 1) {
            float ov = __shfl_down_sync(0xffffffffu, bv, off);
            int   oi = __shfl_down_sync(0xffffffffu, bi, off);
            if (ov > bv || (ov == bv && oi < bi)) { bv = ov; bi = oi; }
        }
        if (tx == 0) {
            int cy = blockIdx.y * 4 + br;
            int cx = blockIdx.x * 4 + bc;
            g_cval[b * NCAND + cy * 64 + cx] = bv;
            g_cidx[b * NCAND + cy * 64 + cx] = bi;
        }
    }
}

// =====================================================================
// Kernel 2: per-image top-500 via 4-round radix select, parallel scan
// =====================================================================
__global__ void __launch_bounds__(512) k_topk() {
    int b = blockIdx.x;
    const float* cv = g_cval + b * NCAND;
    const int*   ci = g_cidx + b * NCAND;
    __shared__ unsigned hist[256];
    __shared__ unsigned scan[256];
    __shared__ unsigned sh_prefix, sh_k, sh_cnt, sh_eqcnt;
    __shared__ int eqidx[256];

    unsigned u[8];
#pragma unroll
    for (int i = 0; i < 8; i++) {
        unsigned bits = __float_as_uint(cv[threadIdx.x + i * 512]);
        u[i] = bits ^ ((bits & 0x80000000u) ? 0xFFFFFFFFu : 0x80000000u);
    }
    if (threadIdx.x == 0) { sh_prefix = 0; sh_k = NTOP; sh_cnt = 0; sh_eqcnt = 0; }

    for (int shift = 24; shift >= 0; shift -= 8) {
        if (threadIdx.x < 256) hist[threadIdx.x] = 0;
        __syncthreads();
        unsigned pre = sh_prefix;
#pragma unroll
        for (int i = 0; i < 8; i++) {
            if (((unsigned long long)u[i] >> (shift + 8)) == (unsigned long long)pre)
                atomicAdd(&hist[(u[i] >> shift) & 255u], 1u);
        }
        __syncthreads();
        if (threadIdx.x < 256) scan[threadIdx.x] = hist[threadIdx.x];
        __syncthreads();
        for (int off = 1; off < 256; off <<= 1) {
            unsigned add = 0;
            if (threadIdx.x < 256 && threadIdx.x + off < 256)
                add = scan[threadIdx.x + off];
            __syncthreads();
            if (threadIdx.x < 256) scan[threadIdx.x] += add;
            __syncthreads();
        }
        if (threadIdx.x < 256) {
            unsigned k = sh_k;
            unsigned Sq  = scan[threadIdx.x];
            unsigned Sq1 = (threadIdx.x == 255) ? 0u : scan[threadIdx.x + 1];
            if (Sq >= k && Sq1 < k) {
                sh_k = k - Sq1;
                sh_prefix = (pre << 8) | (unsigned)threadIdx.x;
            }
        }
        __syncthreads();
    }

    unsigned uth = sh_prefix;
    int kneed = (int)sh_k;
    float thresh = (uth & 0x80000000u) ? __uint_as_float(uth ^ 0x80000000u)
                                       : __uint_as_float(~uth);

    if (thresh > 0.f) {
#pragma unroll
        for (int i = 0; i < 8; i++) {
            int idx = threadIdx.x + i * 512;
            if (u[i] > uth) {
                unsigned p = atomicAdd(&sh_cnt, 1u);
                if (p < NTOP) g_pts[b * NTOP + p] = ci[idx];
            } else if (u[i] == uth) {
                unsigned p = atomicAdd(&sh_eqcnt, 1u);
                if (p < 256) eqidx[p] = ci[idx];
            }
        }
        __syncthreads();
        if (threadIdx.x == 0) {
            int base = min((int)sh_cnt, NTOP);
            int nn = min((int)sh_eqcnt, 256);
            int added = 0;
            while (added < kneed && added < nn) {
                int best = -1, bi2 = 0x7fffffff;
                for (int q = 0; q < nn; q++)
                    if (eqidx[q] >= 0 && eqidx[q] < bi2) { bi2 = eqidx[q]; best = q; }
                if (best < 0) break;
                if (base + added < NTOP) g_pts[b * NTOP + base + added] = bi2;
                eqidx[best] = -1;
                added++;
            }
            g_npt[b] = min(base + added, NTOP);
        }
    } else {
#pragma unroll
        for (int i = 0; i < 8; i++) {
            int idx = threadIdx.x + i * 512;
            if (u[i] > 0x80000000u) {               // ordered form of +0.0
                unsigned p = atomicAdd(&sh_cnt, 1u);
                if (p < NTOP) g_pts[b * NTOP + p] = ci[idx];
            }
        }
        __syncthreads();
        if (threadIdx.x == 0) g_npt[b] = min((int)sh_cnt, NTOP);
    }
}

// =====================================================================
// Kernel 3: dense part — sum(-log1mp) and reg = p*exp(-lap), tiled 32x32
// =====================================================================
__global__ void __launch_bounds__(1024) k_dense(const float* __restrict__ sc) {
    __shared__ float s[36*36];
    __shared__ float h[36*32];
    __shared__ double w1[32], w2[32];
    int b = blockIdx.z, i0 = blockIdx.y * 32, j0 = blockIdx.x * 32;
    int tx = threadIdx.x, ty = threadIdx.y, t = ty*32 + tx;
    const float* P = sc + (size_t)b * HWL;
    for (int idx = t; idx < 36*36; idx += 1024) {
        int a = idx / 36, c = idx % 36;
        s[idx] = P[refl(i0 - 2 + a, HH) * WW + refl(j0 - 2 + c, WW)];
    }
    __syncthreads();
    for (int idx = t; idx < 36*32; idx += 1024) {
        int r = idx / 32, c = idx % 32;
        float x = s[r*36 + c];
#pragma unroll
        for (int k = 1; k < 5; k++) x += s[r*36 + c + k];
        h[idx] = x;
    }
    __syncthreads();
    float p = s[(ty+2)*36 + tx + 2];
    float box = h[ty*32 + tx];
#pragma unroll
    for (int k = 1; k < 5; k++) box += h[(ty+k)*32 + tx];
    float lap = (box - 25.f * p) * (1.f / 48.f);
    double reg = (double)(p * expf(-lap));
    double bce = (double)(-fmaxf(log1pf(-p), -100.f));
    for (int off = 16; off; off >>= 1) {
        bce += __shfl_down_sync(0xffffffffu, bce, off);
        reg += __shfl_down_sync(0xffffffffu, reg, off);
    }
    if ((t & 31) == 0) { w1[t >> 5] = bce; w2[t >> 5] = reg; }
    __syncthreads();
    if (t < 32) {
        bce = w1[t]; reg = w2[t];
        for (int off = 16; off; off >>= 1) {
            bce += __shfl_down_sync(0xffffffffu, bce, off);
            reg += __shfl_down_sync(0xffffffffu, reg, off);
        }
        if (t == 0) {
            int tile = (b * 16 + blockIdx.y) * 16 + blockIdx.x;
            g_pA[tile] = bce; g_pB[tile] = reg;
        }
    }
}

// =====================================================================
// Kernel 4: sparse corner-BCE, warp-per-point (lanes cover 49 taps)
// =====================================================================
__global__ void k_sparse(const float* __restrict__ sc) {
    int b = blockIdx.y;
    int n = g_npt[b];
    const float* P = sc + (size_t)b * HWL;
    int warpsPerImg = gridDim.x * (blockDim.x >> 5);
    int gw = blockIdx.x * (blockDim.x >> 5) + (threadIdx.x >> 5);
    int lane = threadIdx.x & 31;
    double acc = 0.0;
    for (int q = gw; q < n; q += warpsPerImg) {
        int pix = g_pts[b*NTOP + q];
        int pi = pix >> 9, pj = pix & 511;
#pragma unroll
        for (int half = 0; half < 2; half++) {
            int tap = lane + 32 * half;
            if (tap >= 49) break;
            int kr = tap / 7, kc = tap - kr * 7;
            int R = pi - 3 + kr, C = pj - 3 + kc;
            if (R < 0 || R >= HH || C < 0 || C >= WW) continue;
            float wrow = GW[kr];
            if (pi >= 1 && pi <= 3) {
                int d = -pi - R;
                if (d >= -3 && d <= 3) wrow += GW[d+3];
            }
            if (pi >= HH-4 && pi <= HH-2) {
                int d = 2*HH - 2 - pi - R;
                if (d >= -3 && d <= 3) wrow += GW[d+3];
            }
            float wcol = GW[kc];
            if (pj >= 1 && pj <= 3) {
                int d = -pj - C;
                if (d >= -3 && d <= 3) wcol += GW[d+3];
            }
            if (pj >= WW-4 && pj <= WW-2) {
                int d = 2*WW - 2 - pj - C;
                if (d >= -3 && d <= 3) wcol += GW[d+3];
            }
            float pv = P[R*WW + C];
            float lg = fmaxf(logf(pv), -100.f);
            float l1 = fmaxf(log1pf(-pv), -100.f);
            acc += (double)((wrow * wcol) * (l1 - lg));
        }
    }
    __shared__ double wsum[8];
    int wid = threadIdx.x >> 5;
    for (int off = 16; off; off >>= 1) acc += __shfl_down_sync(0xffffffffu, acc, off);
    if (lane == 0) wsum[wid] = acc;
    __syncthreads();
    if (threadIdx.x == 0) {
        double s2 = 0;
        for (int k = 0; k < (int)(blockDim.x >> 5); k++) s2 += wsum[k];
        atomicAdd(&g_accS, s2);
    }
}

// =====================================================================
// Kernel 5: final reduce — 1024 threads, 4 grid-stride rounds, shuffle tree
// =====================================================================
__global__ void __launch_bounds__(1024) k_fin(float* __restrict__ out) {
    double a = 0, r = 0;
#pragma unroll
    for (int k = 0; k < 4; k++) {
        int i = threadIdx.x + k * 1024;
        a += g_pA[i]; r += g_pB[i];
    }
    int lane = threadIdx.x & 31, wid = threadIdx.x >> 5;
    for (int off = 16; off; off >>= 1) {
        a += __shfl_down_sync(0xffffffffu, a, off);
        r += __shfl_down_sync(0xffffffffu, r, off);
    }
    __shared__ double sa[32], sr[32];
    if (lane == 0) { sa[wid] = a; sr[wid] = r; }
    __syncthreads();
    if (wid == 0) {
        a = sa[lane]; r = sr[lane];
        for (int off = 16; off; off >>= 1) {
            a += __shfl_down_sync(0xffffffffu, a, off);
            r += __shfl_down_sync(0xffffffffu, r, off);
        }
        if (lane == 0)
            out[0] = (float)(((a + g_accS) + 10.0 * r) / (double)NTOT);
    }
}

// ---------------- streams/events for fork-join overlap ----------------
struct HxStreams {
    cudaStream_t side;
    cudaEvent_t evFork, evJoin;
    HxStreams() {
        cudaStreamCreateWithFlags(&side, cudaStreamNonBlocking);
        cudaEventCreateWithFlags(&evFork, cudaEventDisableTiming);
        cudaEventCreateWithFlags(&evJoin, cudaEventDisableTiming);
    }
};
static HxStreams g_hx;

// =====================================================================
extern "C" void kernel_launch(void* const* d_in, const int* in_sizes, int n_in,
                              void* d_out, int out_size) {
    const float* scores = (const float*)d_in[0];
    const float* imgs   = (const float*)d_in[1];
    if (n_in >= 2 && in_sizes[0] > in_sizes[1]) {
        scores = (const float*)d_in[1];
        imgs   = (const float*)d_in[0];
    }
    float* out = (float*)d_out;

    // fork: dense pass runs concurrently with gftt->topk->sparse chain
    cudaEventRecord(g_hx.evFork, 0);
    cudaStreamWaitEvent(g_hx.side, g_hx.evFork, 0);
    k_dense<<<dim3(16, 16, BB), dim3(32, 32), 0, g_hx.side>>>(scores);
    cudaEventRecord(g_hx.evJoin, g_hx.side);

    k_gftt<<<dim3(16, 16, BB), 256>>>(imgs);
    k_topk<<<BB, 512>>>();
    k_sparse<<<dim3(32, BB), 256>>>(scores);

    // join
    cudaStreamWaitEvent(0, g_hx.evJoin, 0);
    k_fin<<<1, 1024>>>(out);
    (void)out_size;
}

// round 13
// speedup vs baseline: 1.2052x; 1.0461x over previous
#include <cuda_runtime.h>
#include <math.h>

#define BB 16
#define HH 512
#define WW 512
#define HWL (HH*WW)
#define NTOT (BB*HWL)
#define NCAND 4096
#define NTOP 500
#define NTILE 4096   // 16 imgs * 16*16 dense tiles

// ------------- device scratch (no allocations) -------------
__device__ float  g_cval[BB*NCAND];
__device__ int    g_cidx[BB*NCAND];
__device__ int    g_pts[BB*NTOP];
__device__ int    g_npt[BB];
__device__ double g_pA[NTILE];
__device__ double g_pB[NTILE];
__device__ double g_accS;

// gaussian(7, sigma=1) weights as literals (FFMA-imm)
#define W0 0.004433048f
#define W1 0.054005582f
#define W2 0.242036223f
#define W3 0.399050277f

__constant__ float GW[7] = {W0, W1, W2, W3, W2, W1, W0};

__device__ __forceinline__ int refl(int t, int n) {   // reflect101
    if (t < 0) t = -t;
    if (t >= n) t = 2 * n - 2 - t;
    return t;
}

// =====================================================================
// Kernel 1: fused gray->sobel->gauss7(structure tensor)->GFTT->NMS->
//           per-8x8-block argmax.  32x32 tile, 256 threads.
// smem overlays (floats), total 8064 = 31.5 KB:
//   D0=0(1764) D1=1764(1764)            [42x42 dx, dy]
//   GR=3528(1936)                        [44x44] (dead after sobel)
//   B0=3528 B1=5040 B2=6552 ..8064      [42x36] (overlay GR)
//   SS=0(1296)                           [36x36] (overlay D0; D dead)
//   RM=1296(1152)                        [36x32] (overlay D)
// blurV: register-blocked column sweep (3 out rows / task, 9 LDS/px)
// =====================================================================
__global__ void __launch_bounds__(256) k_gftt(const float* __restrict__ imgs) {
    __shared__ float sm[8064];
    float* D0 = sm;
    float* D1 = sm + 1764;
    float* GR = sm + 3528;
    float* B0 = sm + 3528;
    float* B1 = sm + 5040;
    float* B2 = sm + 6552;
    float* SS = sm;
    float* RM = sm + 1296;

    int b  = blockIdx.z;
    int i0 = blockIdx.y * 32, j0 = blockIdx.x * 32;
    int t  = threadIdx.x;
    int tx = t & 31, tw = t >> 5;
    if (b == 0 && blockIdx.x == 0 && blockIdx.y == 0 && t == 0) g_accS = 0.0;

    const float* img = imgs + (size_t)b * 3 * HWL;

    // --- gray: 44 x 44 (clamped coords) ---
    for (int r = tw; r < 44; r += 8) {
        int gi = min(max(i0 - 6 + r, 0), HH - 1);
        {
            int c = tx;
            int gj = min(max(j0 - 6 + c, 0), WW - 1);
            int p = gi * WW + gj;
            GR[r*44 + c] = 0.299f*img[p] + 0.587f*img[HWL+p] + 0.114f*img[2*HWL+p];
        }
        if (tx < 12) {
            int c = tx + 32;
            int gj = min(max(j0 - 6 + c, 0), WW - 1);
            int p = gi * WW + gj;
            GR[r*44 + c] = 0.299f*img[p] + 0.587f*img[HWL+p] + 0.114f*img[2*HWL+p];
        }
    }
    __syncthreads();

    // --- sobel dx,dy: 42 x 42 at reflected coords ---
    for (int r = tw; r < 42; r += 8) {
        int rg = refl(i0 - 5 + r, HH);
        int rm_ = max(rg - 1, 0) - (i0 - 6);
        int r0_ = rg - (i0 - 6);
        int rp_ = min(rg + 1, HH - 1) - (i0 - 6);
#pragma unroll
        for (int m = 0; m < 2; m++) {
            int c = tx + 32 * m;
            if (c < 42) {
                int cg = refl(j0 - 5 + c, WW);
                int cm_ = max(cg - 1, 0) - (j0 - 6);
                int c0_ = cg - (j0 - 6);
                int cp_ = min(cg + 1, WW - 1) - (j0 - 6);
                float A = GR[rm_*44+cm_], Bv = GR[rm_*44+c0_], C = GR[rm_*44+cp_];
                float D = GR[r0_*44+cm_],                      F = GR[r0_*44+cp_];
                float G = GR[rp_*44+cm_], H  = GR[rp_*44+c0_], K = GR[rp_*44+cp_];
                int o = r * 42 + c;
                D0[o] = (C - A + 2.f*(F - D) + K - G) * 0.125f;
                D1[o] = (G - A + 2.f*(H - Bv) + K - C) * 0.125f;
            }
        }
    }
    __syncthreads();

    // --- horizontal gauss7 on products (formed on the fly): 42 x 36 ---
    for (int r = tw; r < 42; r += 8) {
#pragma unroll
        for (int m = 0; m < 2; m++) {
            int c = tx + 32 * m;
            if (c < 36) {
                int base = r * 42 + c;
                float s0, s1, s2;
                {
                    float dx = D0[base], dy = D1[base];
                    s0 = W0 * (dx*dx); s1 = W0 * (dy*dy); s2 = W0 * (dx*dy);
                }
#define HTAP(Q, WQ) { float dx = D0[base+Q], dy = D1[base+Q]; \
                      s0 += WQ * (dx*dx); s1 += WQ * (dy*dy); s2 += WQ * (dx*dy); }
                HTAP(1, W1) HTAP(2, W2) HTAP(3, W3) HTAP(4, W2) HTAP(5, W1) HTAP(6, W0)
#undef HTAP
                int o = r * 36 + c;
                B0[o] = s0; B1[o] = s1; B2[o] = s2;
            }
        }
    }
    __syncthreads();

    // --- vertical gauss7 + GFTT response: 36 x 36 ---
    // register-blocked column sweep: 12 segs x 36 cols = 432 tasks,
    // each task: 3 output rows in one column; 9 input rows loaded once.
#pragma unroll
    for (int k2 = 0; k2 < 2; k2++) {
        int idx = t + k2 * 256;
        if (idx < 432) {
            int seg = idx / 36;
            int c = idx - seg * 36;
            int r0 = seg * 3;
            float v0[9], v1[9], v2[9];
#pragma unroll
            for (int q = 0; q < 9; q++) {
                int row = (r0 + q) * 36 + c;
                v0[q] = B0[row]; v1[q] = B1[row]; v2[q] = B2[row];
            }
#pragma unroll
            for (int rr = 0; rr < 3; rr++) {
                float a  = W0*(v0[rr]+v0[rr+6]) + W1*(v0[rr+1]+v0[rr+5])
                         + W2*(v0[rr+2]+v0[rr+4]) + W3*v0[rr+3];
                float cc = W0*(v1[rr]+v1[rr+6]) + W1*(v1[rr+1]+v1[rr+5])
                         + W2*(v1[rr+2]+v1[rr+4]) + W3*v1[rr+3];
                float e  = W0*(v2[rr]+v2[rr+6]) + W1*(v2[rr+1]+v2[rr+5])
                         + W2*(v2[rr+2]+v2[rr+4]) + W3*v2[rr+3];
                float det = a * cc - e * e, tr = a + cc;
                float s = 0.5f * (tr - sqrtf(fabsf(tr * tr - 4.f * det)));
                int gi = i0 - 2 + r0 + rr, gj = j0 - 2 + c;
                SS[(r0 + rr) * 36 + c] =
                    (gi >= 0 && gi < HH && gj >= 0 && gj < WW) ? s : -INFINITY;
            }
        }
    }
    __syncthreads();

    // --- NMS row-max: 36 x 32 ---
    for (int r = tw; r < 36; r += 8) {
        float mx = SS[r * 36 + tx];
#pragma unroll
        for (int q = 1; q < 5; q++) mx = fmaxf(mx, SS[r * 36 + tx + q]);
        RM[r * 32 + tx] = mx;
    }
    __syncthreads();

    // --- per-pixel NMS + 8x8 block argmax: warp tw handles blocks 2tw, 2tw+1 ---
#pragma unroll
    for (int k = 0; k < 2; k++) {
        int bb = 2 * tw + k;
        int br = bb >> 2, bc = bb & 3;
        float bv = -1.f; int bi = 0x7fffffff;
#pragma unroll
        for (int h = 0; h < 2; h++) {
            int e = tx + 32 * h;
            int r = br * 8 + (e >> 3), c = bc * 8 + (e & 7);
            float s = SS[(r + 2) * 36 + c + 2];
            float mx = RM[r * 32 + c];
#pragma unroll
            for (int q = 1; q < 5; q++) mx = fmaxf(mx, RM[(r + q) * 32 + c]);
            float v = (s == mx) ? s : 0.f;
            int gix = (i0 + r) * WW + (j0 + c);
            if (v > bv || (v == bv && gix < bi)) { bv = v; bi = gix; }
        }
#pragma unroll
        for (int off = 16; off >= 1; off >>= 1) {
            float ov = __shfl_down_sync(0xffffffffu, bv, off);
            int   oi = __shfl_down_sync(0xffffffffu, bi, off);
            if (ov > bv || (ov == bv && oi < bi)) { bv = ov; bi = oi; }
        }
        if (tx == 0) {
            int cy = blockIdx.y * 4 + br;
            int cx = blockIdx.x * 4 + bc;
            g_cval[b * NCAND + cy * 64 + cx] = bv;
            g_cidx[b * NCAND + cy * 64 + cx] = bi;
        }
    }
}

// =====================================================================
// Kernel 2: per-image top-500 via 4-round radix select, parallel scan
// =====================================================================
__global__ void __launch_bounds__(512) k_topk() {
    int b = blockIdx.x;
    const float* cv = g_cval + b * NCAND;
    const int*   ci = g_cidx + b * NCAND;
    __shared__ unsigned hist[256];
    __shared__ unsigned scan[256];
    __shared__ unsigned sh_prefix, sh_k, sh_cnt, sh_eqcnt;
    __shared__ int eqidx[256];

    unsigned u[8];
#pragma unroll
    for (int i = 0; i < 8; i++) {
        unsigned bits = __float_as_uint(cv[threadIdx.x + i * 512]);
        u[i] = bits ^ ((bits & 0x80000000u) ? 0xFFFFFFFFu : 0x80000000u);
    }
    if (threadIdx.x == 0) { sh_prefix = 0; sh_k = NTOP; sh_cnt = 0; sh_eqcnt = 0; }

    for (int shift = 24; shift >= 0; shift -= 8) {
        if (threadIdx.x < 256) hist[threadIdx.x] = 0;
        __syncthreads();
        unsigned pre = sh_prefix;
#pragma unroll
        for (int i = 0; i < 8; i++) {
            if (((unsigned long long)u[i] >> (shift + 8)) == (unsigned long long)pre)
                atomicAdd(&hist[(u[i] >> shift) & 255u], 1u);
        }
        __syncthreads();
        if (threadIdx.x < 256) scan[threadIdx.x] = hist[threadIdx.x];
        __syncthreads();
        for (int off = 1; off < 256; off <<= 1) {
            unsigned add = 0;
            if (threadIdx.x < 256 && threadIdx.x + off < 256)
                add = scan[threadIdx.x + off];
            __syncthreads();
            if (threadIdx.x < 256) scan[threadIdx.x] += add;
            __syncthreads();
        }
        if (threadIdx.x < 256) {
            unsigned k = sh_k;
            unsigned Sq  = scan[threadIdx.x];
            unsigned Sq1 = (threadIdx.x == 255) ? 0u : scan[threadIdx.x + 1];
            if (Sq >= k && Sq1 < k) {
                sh_k = k - Sq1;
                sh_prefix = (pre << 8) | (unsigned)threadIdx.x;
            }
        }
        __syncthreads();
    }

    unsigned uth = sh_prefix;
    int kneed = (int)sh_k;
    float thresh = (uth & 0x80000000u) ? __uint_as_float(uth ^ 0x80000000u)
                                       : __uint_as_float(~uth);

    if (thresh > 0.f) {
#pragma unroll
        for (int i = 0; i < 8; i++) {
            int idx = threadIdx.x + i * 512;
            if (u[i] > uth) {
                unsigned p = atomicAdd(&sh_cnt, 1u);
                if (p < NTOP) g_pts[b * NTOP + p] = ci[idx];
            } else if (u[i] == uth) {
                unsigned p = atomicAdd(&sh_eqcnt, 1u);
                if (p < 256) eqidx[p] = ci[idx];
            }
        }
        __syncthreads();
        if (threadIdx.x == 0) {
            int base = min((int)sh_cnt, NTOP);
            int nn = min((int)sh_eqcnt, 256);
            int added = 0;
            while (added < kneed && added < nn) {
                int best = -1, bi2 = 0x7fffffff;
                for (int q = 0; q < nn; q++)
                    if (eqidx[q] >= 0 && eqidx[q] < bi2) { bi2 = eqidx[q]; best = q; }
                if (best < 0) break;
                if (base + added < NTOP) g_pts[b * NTOP + base + added] = bi2;
                eqidx[best] = -1;
                added++;
            }
            g_npt[b] = min(base + added, NTOP);
        }
    } else {
#pragma unroll
        for (int i = 0; i < 8; i++) {
            int idx = threadIdx.x + i * 512;
            if (u[i] > 0x80000000u) {               // ordered form of +0.0
                unsigned p = atomicAdd(&sh_cnt, 1u);
                if (p < NTOP) g_pts[b * NTOP + p] = ci[idx];
            }
        }
        __syncthreads();
        if (threadIdx.x == 0) g_npt[b] = min((int)sh_cnt, NTOP);
    }
}

// =====================================================================
// Kernel 3: dense part — sum(-log1mp) and reg = p*exp(-lap), tiled 32x32
// =====================================================================
__global__ void __launch_bounds__(1024) k_dense(const float* __restrict__ sc) {
    __shared__ float s[36*36];
    __shared__ float h[36*32];
    __shared__ double w1[32], w2[32];
    int b = blockIdx.z, i0 = blockIdx.y * 32, j0 = blockIdx.x * 32;
    int tx = threadIdx.x, ty = threadIdx.y, t = ty*32 + tx;
    const float* P = sc + (size_t)b * HWL;
    for (int idx = t; idx < 36*36; idx += 1024) {
        int a = idx / 36, c = idx % 36;
        s[idx] = P[refl(i0 - 2 + a, HH) * WW + refl(j0 - 2 + c, WW)];
    }
    __syncthreads();
    for (int idx = t; idx < 36*32; idx += 1024) {
        int r = idx / 32, c = idx % 32;
        float x = s[r*36 + c];
#pragma unroll
        for (int k = 1; k < 5; k++) x += s[r*36 + c + k];
        h[idx] = x;
    }
    __syncthreads();
    float p = s[(ty+2)*36 + tx + 2];
    float box = h[ty*32 + tx];
#pragma unroll
    for (int k = 1; k < 5; k++) box += h[(ty+k)*32 + tx];
    float lap = (box - 25.f * p) * (1.f / 48.f);
    double reg = (double)(p * expf(-lap));
    double bce = (double)(-fmaxf(log1pf(-p), -100.f));
    for (int off = 16; off; off >>= 1) {
        bce += __shfl_down_sync(0xffffffffu, bce, off);
        reg += __shfl_down_sync(0xffffffffu, reg, off);
    }
    if ((t & 31) == 0) { w1[t >> 5] = bce; w2[t >> 5] = reg; }
    __syncthreads();
    if (t < 32) {
        bce = w1[t]; reg = w2[t];
        for (int off = 16; off; off >>= 1) {
            bce += __shfl_down_sync(0xffffffffu, bce, off);
            reg += __shfl_down_sync(0xffffffffu, reg, off);
        }
        if (t == 0) {
            int tile = (b * 16 + blockIdx.y) * 16 + blockIdx.x;
            g_pA[tile] = bce; g_pB[tile] = reg;
        }
    }
}

// =====================================================================
// Kernel 4: sparse corner-BCE, warp-per-point (lanes cover 49 taps)
// =====================================================================
__global__ void k_sparse(const float* __restrict__ sc) {
    int b = blockIdx.y;
    int n = g_npt[b];
    const float* P = sc + (size_t)b * HWL;
    int warpsPerImg = gridDim.x * (blockDim.x >> 5);
    int gw = blockIdx.x * (blockDim.x >> 5) + (threadIdx.x >> 5);
    int lane = threadIdx.x & 31;
    double acc = 0.0;
    for (int q = gw; q < n; q += warpsPerImg) {
        int pix = g_pts[b*NTOP + q];
        int pi = pix >> 9, pj = pix & 511;
#pragma unroll
        for (int half = 0; half < 2; half++) {
            int tap = lane + 32 * half;
            if (tap >= 49) break;
            int kr = tap / 7, kc = tap - kr * 7;
            int R = pi - 3 + kr, C = pj - 3 + kc;
            if (R < 0 || R >= HH || C < 0 || C >= WW) continue;
            float wrow = GW[kr];
            if (pi >= 1 && pi <= 3) {
                int d = -pi - R;
                if (d >= -3 && d <= 3) wrow += GW[d+3];
            }
            if (pi >= HH-4 && pi <= HH-2) {
                int d = 2*HH - 2 - pi - R;
                if (d >= -3 && d <= 3) wrow += GW[d+3];
            }
            float wcol = GW[kc];
            if (pj >= 1 && pj <= 3) {
                int d = -pj - C;
                if (d >= -3 && d <= 3) wcol += GW[d+3];
            }
            if (pj >= WW-4 && pj <= WW-2) {
                int d = 2*WW - 2 - pj - C;
                if (d >= -3 && d <= 3) wcol += GW[d+3];
            }
            float pv = P[R*WW + C];
            float lg = fmaxf(logf(pv), -100.f);
            float l1 = fmaxf(log1pf(-pv), -100.f);
            acc += (double)((wrow * wcol) * (l1 - lg));
        }
    }
    __shared__ double wsum[8];
    int wid = threadIdx.x >> 5;
    for (int off = 16; off; off >>= 1) acc += __shfl_down_sync(0xffffffffu, acc, off);
    if (lane == 0) wsum[wid] = acc;
    __syncthreads();
    if (threadIdx.x == 0) {
        double s2 = 0;
        for (int k = 0; k < (int)(blockDim.x >> 5); k++) s2 += wsum[k];
        atomicAdd(&g_accS, s2);
    }
}

// =====================================================================
// Kernel 5: final reduce — 1024 threads, shuffle tree
// =====================================================================
__global__ void __launch_bounds__(1024) k_fin(float* __restrict__ out) {
    double a = 0, r = 0;
#pragma unroll
    for (int k = 0; k < 4; k++) {
        int i = threadIdx.x + k * 1024;
        a += g_pA[i]; r += g_pB[i];
    }
    int lane = threadIdx.x & 31, wid = threadIdx.x >> 5;
    for (int off = 16; off; off >>= 1) {
        a += __shfl_down_sync(0xffffffffu, a, off);
        r += __shfl_down_sync(0xffffffffu, r, off);
    }
    __shared__ double sa[32], sr[32];
    if (lane == 0) { sa[wid] = a; sr[wid] = r; }
    __syncthreads();
    if (wid == 0) {
        a = sa[lane]; r = sr[lane];
        for (int off = 16; off; off >>= 1) {
            a += __shfl_down_sync(0xffffffffu, a, off);
            r += __shfl_down_sync(0xffffffffu, r, off);
        }
        if (lane == 0)
            out[0] = (float)(((a + g_accS) + 10.0 * r) / (double)NTOT);
    }
}

// ---------------- streams/events for fork-join overlap ----------------
struct HxStreams {
    cudaStream_t side;
    cudaEvent_t evFork, evJoin;
    HxStreams() {
        cudaStreamCreateWithFlags(&side, cudaStreamNonBlocking);
        cudaEventCreateWithFlags(&evFork, cudaEventDisableTiming);
        cudaEventCreateWithFlags(&evJoin, cudaEventDisableTiming);
    }
};
static HxStreams g_hx;

// =====================================================================
extern "C" void kernel_launch(void* const* d_in, const int* in_sizes, int n_in,
                              void* d_out, int out_size) {
    const float* scores = (const float*)d_in[0];
    const float* imgs   = (const float*)d_in[1];
    if (n_in >= 2 && in_sizes[0] > in_sizes[1]) {
        scores = (const float*)d_in[1];
        imgs   = (const float*)d_in[0];
    }
    float* out = (float*)d_out;

    // fork: dense pass runs concurrently with gftt->topk->sparse chain
    cudaEventRecord(g_hx.evFork, 0);
    cudaStreamWaitEvent(g_hx.side, g_hx.evFork, 0);
    k_dense<<<dim3(16, 16, BB), dim3(32, 32), 0, g_hx.side>>>(scores);
    cudaEventRecord(g_hx.evJoin, g_hx.side);

    k_gftt<<<dim3(16, 16, BB), 256>>>(imgs);
    k_topk<<<BB, 512>>>();
    k_sparse<<<dim3(32, BB), 256>>>(scores);

    // join
    cudaStreamWaitEvent(0, g_hx.evJoin, 0);
    k_fin<<<1, 1024>>>(out);
    (void)out_size;
}

// round 14
// speedup vs baseline: 1.2614x; 1.0466x over previous
#include <cuda_runtime.h>
#include <math.h>

#define BB 16
#define HH 512
#define WW 512
#define HWL (HH*WW)
#define NTOT (BB*HWL)
#define NCAND 4096
#define NTOP 500
#define NTILE 4096   // 16 imgs * 16*16 dense tiles

// ------------- device scratch (no allocations) -------------
__device__ float  g_cval[BB*NCAND];
__device__ int    g_cidx[BB*NCAND];
__device__ int    g_pts[BB*NTOP];
__device__ int    g_npt[BB];
__device__ double g_pA[NTILE];
__device__ double g_pB[NTILE];
__device__ double g_accS;

// gaussian(7, sigma=1) weights as literals (FFMA-imm)
#define W0 0.004433048f
#define W1 0.054005582f
#define W2 0.242036223f
#define W3 0.399050277f

__constant__ float GW[7] = {W0, W1, W2, W3, W2, W1, W0};

__device__ __forceinline__ int refl(int t, int n) {   // reflect101
    if (t < 0) t = -t;
    if (t >= n) t = 2 * n - 2 - t;
    return t;
}

// =====================================================================
// Kernel 1: fused gray->sobel->gauss7(structure tensor)->GFTT->NMS->
//           per-8x8-block argmax.  32x32 tile, 256 threads.
// smem overlays (floats), total 8064 = 31.5 KB:
//   D0=0(1764) D1=1764(1764)            [42x42 dx, dy]
//   GR=3528(1936)                        [44x44] (dead after sobel)
//   B0=3528 B1=5040 B2=6552 ..8064      [42x36] (overlay GR)
//   SS=0(1296)                           [36x36] (overlay D0; D dead)
//   RM=1296(1152)                        [36x32] (overlay D)
// blurH: register-blocked 3-col segments (6 LDS/px)
// blurV: register-blocked column sweep (9 LDS/px)
// =====================================================================
__global__ void __launch_bounds__(256) k_gftt(const float* __restrict__ imgs) {
    __shared__ float sm[8064];
    float* D0 = sm;
    float* D1 = sm + 1764;
    float* GR = sm + 3528;
    float* B0 = sm + 3528;
    float* B1 = sm + 5040;
    float* B2 = sm + 6552;
    float* SS = sm;
    float* RM = sm + 1296;

    int b  = blockIdx.z;
    int i0 = blockIdx.y * 32, j0 = blockIdx.x * 32;
    int t  = threadIdx.x;
    int tx = t & 31, tw = t >> 5;
    if (b == 0 && blockIdx.x == 0 && blockIdx.y == 0 && t == 0) g_accS = 0.0;

    const float* img = imgs + (size_t)b * 3 * HWL;

    // --- gray: 44 x 44 (clamped coords) ---
    for (int r = tw; r < 44; r += 8) {
        int gi = min(max(i0 - 6 + r, 0), HH - 1);
        {
            int c = tx;
            int gj = min(max(j0 - 6 + c, 0), WW - 1);
            int p = gi * WW + gj;
            GR[r*44 + c] = 0.299f*img[p] + 0.587f*img[HWL+p] + 0.114f*img[2*HWL+p];
        }
        if (tx < 12) {
            int c = tx + 32;
            int gj = min(max(j0 - 6 + c, 0), WW - 1);
            int p = gi * WW + gj;
            GR[r*44 + c] = 0.299f*img[p] + 0.587f*img[HWL+p] + 0.114f*img[2*HWL+p];
        }
    }
    __syncthreads();

    // --- sobel dx,dy: 42 x 42 at reflected coords ---
    for (int r = tw; r < 42; r += 8) {
        int rg = refl(i0 - 5 + r, HH);
        int rm_ = max(rg - 1, 0) - (i0 - 6);
        int r0_ = rg - (i0 - 6);
        int rp_ = min(rg + 1, HH - 1) - (i0 - 6);
#pragma unroll
        for (int m = 0; m < 2; m++) {
            int c = tx + 32 * m;
            if (c < 42) {
                int cg = refl(j0 - 5 + c, WW);
                int cm_ = max(cg - 1, 0) - (j0 - 6);
                int c0_ = cg - (j0 - 6);
                int cp_ = min(cg + 1, WW - 1) - (j0 - 6);
                float A = GR[rm_*44+cm_], Bv = GR[rm_*44+c0_], C = GR[rm_*44+cp_];
                float D = GR[r0_*44+cm_],                      F = GR[r0_*44+cp_];
                float G = GR[rp_*44+cm_], H  = GR[rp_*44+c0_], K = GR[rp_*44+cp_];
                int o = r * 42 + c;
                D0[o] = (C - A + 2.f*(F - D) + K - G) * 0.125f;
                D1[o] = (G - A + 2.f*(H - Bv) + K - C) * 0.125f;
            }
        }
    }
    __syncthreads();

    // --- horizontal gauss7 on products: register-blocked 3-col segments ---
    // 42 rows x 12 segments = 504 tasks; each loads 9 D0 + 9 D1 once,
    // forms products, emits 3 outputs with symmetric weight folding.
#pragma unroll
    for (int k2 = 0; k2 < 2; k2++) {
        int idx = t + k2 * 256;
        if (idx < 504) {
            int r = idx / 12;
            int seg = idx - r * 12;
            int c0 = seg * 3;
            int base = r * 42 + c0;
            float p0[9], p1[9], p2[9];
#pragma unroll
            for (int q = 0; q < 9; q++) {
                float dx = D0[base + q], dy = D1[base + q];
                p0[q] = dx * dx; p1[q] = dy * dy; p2[q] = dx * dy;
            }
            int o = r * 36 + c0;
#pragma unroll
            for (int rr = 0; rr < 3; rr++) {
                float s0 = W0*(p0[rr]+p0[rr+6]) + W1*(p0[rr+1]+p0[rr+5])
                         + W2*(p0[rr+2]+p0[rr+4]) + W3*p0[rr+3];
                float s1 = W0*(p1[rr]+p1[rr+6]) + W1*(p1[rr+1]+p1[rr+5])
                         + W2*(p1[rr+2]+p1[rr+4]) + W3*p1[rr+3];
                float s2 = W0*(p2[rr]+p2[rr+6]) + W1*(p2[rr+1]+p2[rr+5])
                         + W2*(p2[rr+2]+p2[rr+4]) + W3*p2[rr+3];
                B0[o + rr] = s0; B1[o + rr] = s1; B2[o + rr] = s2;
            }
        }
    }
    __syncthreads();

    // --- vertical gauss7 + GFTT response: 36 x 36 ---
    // register-blocked column sweep: 12 segs x 36 cols = 432 tasks,
    // each task: 3 output rows in one column; 9 input rows loaded once.
#pragma unroll
    for (int k2 = 0; k2 < 2; k2++) {
        int idx = t + k2 * 256;
        if (idx < 432) {
            int seg = idx / 36;
            int c = idx - seg * 36;
            int r0 = seg * 3;
            float v0[9], v1[9], v2[9];
#pragma unroll
            for (int q = 0; q < 9; q++) {
                int row = (r0 + q) * 36 + c;
                v0[q] = B0[row]; v1[q] = B1[row]; v2[q] = B2[row];
            }
#pragma unroll
            for (int rr = 0; rr < 3; rr++) {
                float a  = W0*(v0[rr]+v0[rr+6]) + W1*(v0[rr+1]+v0[rr+5])
                         + W2*(v0[rr+2]+v0[rr+4]) + W3*v0[rr+3];
                float cc = W0*(v1[rr]+v1[rr+6]) + W1*(v1[rr+1]+v1[rr+5])
                         + W2*(v1[rr+2]+v1[rr+4]) + W3*v1[rr+3];
                float e  = W0*(v2[rr]+v2[rr+6]) + W1*(v2[rr+1]+v2[rr+5])
                         + W2*(v2[rr+2]+v2[rr+4]) + W3*v2[rr+3];
                float det = a * cc - e * e, tr = a + cc;
                float s = 0.5f * (tr - sqrtf(fabsf(tr * tr - 4.f * det)));
                int gi = i0 - 2 + r0 + rr, gj = j0 - 2 + c;
                SS[(r0 + rr) * 36 + c] =
                    (gi >= 0 && gi < HH && gj >= 0 && gj < WW) ? s : -INFINITY;
            }
        }
    }
    __syncthreads();

    // --- NMS row-max: 36 x 32 ---
    for (int r = tw; r < 36; r += 8) {
        float mx = SS[r * 36 + tx];
#pragma unroll
        for (int q = 1; q < 5; q++) mx = fmaxf(mx, SS[r * 36 + tx + q]);
        RM[r * 32 + tx] = mx;
    }
    __syncthreads();

    // --- per-pixel NMS + 8x8 block argmax: warp tw handles blocks 2tw, 2tw+1 ---
#pragma unroll
    for (int k = 0; k < 2; k++) {
        int bb = 2 * tw + k;
        int br = bb >> 2, bc = bb & 3;
        float bv = -1.f; int bi = 0x7fffffff;
#pragma unroll
        for (int h = 0; h < 2; h++) {
            int e = tx + 32 * h;
            int r = br * 8 + (e >> 3), c = bc * 8 + (e & 7);
            float s = SS[(r + 2) * 36 + c + 2];
            float mx = RM[r * 32 + c];
#pragma unroll
            for (int q = 1; q < 5; q++) mx = fmaxf(mx, RM[(r + q) * 32 + c]);
            float v = (s == mx) ? s : 0.f;
            int gix = (i0 + r) * WW + (j0 + c);
            if (v > bv || (v == bv && gix < bi)) { bv = v; bi = gix; }
        }
#pragma unroll
        for (int off = 16; off >= 1; off >>= 1) {
            float ov = __shfl_down_sync(0xffffffffu, bv, off);
            int   oi = __shfl_down_sync(0xffffffffu, bi, off);
            if (ov > bv || (ov == bv && oi < bi)) { bv = ov; bi = oi; }
        }
        if (tx == 0) {
            int cy = blockIdx.y * 4 + br;
            int cx = blockIdx.x * 4 + bc;
            g_cval[b * NCAND + cy * 64 + cx] = bv;
            g_cidx[b * NCAND + cy * 64 + cx] = bi;
        }
    }
}

// =====================================================================
// Kernel 2: per-image top-500 via 4-round radix select, parallel scan
// =====================================================================
__global__ void __launch_bounds__(512) k_topk() {
    int b = blockIdx.x;
    const float* cv = g_cval + b * NCAND;
    const int*   ci = g_cidx + b * NCAND;
    __shared__ unsigned hist[256];
    __shared__ unsigned scan[256];
    __shared__ unsigned sh_prefix, sh_k, sh_cnt, sh_eqcnt;
    __shared__ int eqidx[256];

    unsigned u[8];
#pragma unroll
    for (int i = 0; i < 8; i++) {
        unsigned bits = __float_as_uint(cv[threadIdx.x + i * 512]);
        u[i] = bits ^ ((bits & 0x80000000u) ? 0xFFFFFFFFu : 0x80000000u);
    }
    if (threadIdx.x == 0) { sh_prefix = 0; sh_k = NTOP; sh_cnt = 0; sh_eqcnt = 0; }

    for (int shift = 24; shift >= 0; shift -= 8) {
        if (threadIdx.x < 256) hist[threadIdx.x] = 0;
        __syncthreads();
        unsigned pre = sh_prefix;
#pragma unroll
        for (int i = 0; i < 8; i++) {
            if (((unsigned long long)u[i] >> (shift + 8)) == (unsigned long long)pre)
                atomicAdd(&hist[(u[i] >> shift) & 255u], 1u);
        }
        __syncthreads();
        if (threadIdx.x < 256) scan[threadIdx.x] = hist[threadIdx.x];
        __syncthreads();
        for (int off = 1; off < 256; off <<= 1) {
            unsigned add = 0;
            if (threadIdx.x < 256 && threadIdx.x + off < 256)
                add = scan[threadIdx.x + off];
            __syncthreads();
            if (threadIdx.x < 256) scan[threadIdx.x] += add;
            __syncthreads();
        }
        if (threadIdx.x < 256) {
            unsigned k = sh_k;
            unsigned Sq  = scan[threadIdx.x];
            unsigned Sq1 = (threadIdx.x == 255) ? 0u : scan[threadIdx.x + 1];
            if (Sq >= k && Sq1 < k) {
                sh_k = k - Sq1;
                sh_prefix = (pre << 8) | (unsigned)threadIdx.x;
            }
        }
        __syncthreads();
    }

    unsigned uth = sh_prefix;
    int kneed = (int)sh_k;
    float thresh = (uth & 0x80000000u) ? __uint_as_float(uth ^ 0x80000000u)
                                       : __uint_as_float(~uth);

    if (thresh > 0.f) {
#pragma unroll
        for (int i = 0; i < 8; i++) {
            int idx = threadIdx.x + i * 512;
            if (u[i] > uth) {
                unsigned p = atomicAdd(&sh_cnt, 1u);
                if (p < NTOP) g_pts[b * NTOP + p] = ci[idx];
            } else if (u[i] == uth) {
                unsigned p = atomicAdd(&sh_eqcnt, 1u);
                if (p < 256) eqidx[p] = ci[idx];
            }
        }
        __syncthreads();
        if (threadIdx.x == 0) {
            int base = min((int)sh_cnt, NTOP);
            int nn = min((int)sh_eqcnt, 256);
            int added = 0;
            while (added < kneed && added < nn) {
                int best = -1, bi2 = 0x7fffffff;
                for (int q = 0; q < nn; q++)
                    if (eqidx[q] >= 0 && eqidx[q] < bi2) { bi2 = eqidx[q]; best = q; }
                if (best < 0) break;
                if (base + added < NTOP) g_pts[b * NTOP + base + added] = bi2;
                eqidx[best] = -1;
                added++;
            }
            g_npt[b] = min(base + added, NTOP);
        }
    } else {
#pragma unroll
        for (int i = 0; i < 8; i++) {
            int idx = threadIdx.x + i * 512;
            if (u[i] > 0x80000000u) {               // ordered form of +0.0
                unsigned p = atomicAdd(&sh_cnt, 1u);
                if (p < NTOP) g_pts[b * NTOP + p] = ci[idx];
            }
        }
        __syncthreads();
        if (threadIdx.x == 0) g_npt[b] = min((int)sh_cnt, NTOP);
    }
}

// =====================================================================
// Kernel 3: dense part — sum(-log1mp) and reg = p*exp(-lap), tiled 32x32
// =====================================================================
__global__ void __launch_bounds__(1024) k_dense(const float* __restrict__ sc) {
    __shared__ float s[36*36];
    __shared__ float h[36*32];
    __shared__ double w1[32], w2[32];
    int b = blockIdx.z, i0 = blockIdx.y * 32, j0 = blockIdx.x * 32;
    int tx = threadIdx.x, ty = threadIdx.y, t = ty*32 + tx;
    const float* P = sc + (size_t)b * HWL;
    for (int idx = t; idx < 36*36; idx += 1024) {
        int a = idx / 36, c = idx % 36;
        s[idx] = P[refl(i0 - 2 + a, HH) * WW + refl(j0 - 2 + c, WW)];
    }
    __syncthreads();
    for (int idx = t; idx < 36*32; idx += 1024) {
        int r = idx / 32, c = idx % 32;
        float x = s[r*36 + c];
#pragma unroll
        for (int k = 1; k < 5; k++) x += s[r*36 + c + k];
        h[idx] = x;
    }
    __syncthreads();
    float p = s[(ty+2)*36 + tx + 2];
    float box = h[ty*32 + tx];
#pragma unroll
    for (int k = 1; k < 5; k++) box += h[(ty+k)*32 + tx];
    float lap = (box - 25.f * p) * (1.f / 48.f);
    double reg = (double)(p * expf(-lap));
    double bce = (double)(-fmaxf(log1pf(-p), -100.f));
    for (int off = 16; off; off >>= 1) {
        bce += __shfl_down_sync(0xffffffffu, bce, off);
        reg += __shfl_down_sync(0xffffffffu, reg, off);
    }
    if ((t & 31) == 0) { w1[t >> 5] = bce; w2[t >> 5] = reg; }
    __syncthreads();
    if (t < 32) {
        bce = w1[t]; reg = w2[t];
        for (int off = 16; off; off >>= 1) {
            bce += __shfl_down_sync(0xffffffffu, bce, off);
            reg += __shfl_down_sync(0xffffffffu, reg, off);
        }
        if (t == 0) {
            int tile = (b * 16 + blockIdx.y) * 16 + blockIdx.x;
            g_pA[tile] = bce; g_pB[tile] = reg;
        }
    }
}

// =====================================================================
// Kernel 4: sparse corner-BCE, warp-per-point (lanes cover 49 taps)
// =====================================================================
__global__ void k_sparse(const float* __restrict__ sc) {
    int b = blockIdx.y;
    int n = g_npt[b];
    const float* P = sc + (size_t)b * HWL;
    int warpsPerImg = gridDim.x * (blockDim.x >> 5);
    int gw = blockIdx.x * (blockDim.x >> 5) + (threadIdx.x >> 5);
    int lane = threadIdx.x & 31;
    double acc = 0.0;
    for (int q = gw; q < n; q += warpsPerImg) {
        int pix = g_pts[b*NTOP + q];
        int pi = pix >> 9, pj = pix & 511;
#pragma unroll
        for (int half = 0; half < 2; half++) {
            int tap = lane + 32 * half;
            if (tap >= 49) break;
            int kr = tap / 7, kc = tap - kr * 7;
            int R = pi - 3 + kr, C = pj - 3 + kc;
            if (R < 0 || R >= HH || C < 0 || C >= WW) continue;
            float wrow = GW[kr];
            if (pi >= 1 && pi <= 3) {
                int d = -pi - R;
                if (d >= -3 && d <= 3) wrow += GW[d+3];
            }
            if (pi >= HH-4 && pi <= HH-2) {
                int d = 2*HH - 2 - pi - R;
                if (d >= -3 && d <= 3) wrow += GW[d+3];
            }
            float wcol = GW[kc];
            if (pj >= 1 && pj <= 3) {
                int d = -pj - C;
                if (d >= -3 && d <= 3) wcol += GW[d+3];
            }
            if (pj >= WW-4 && pj <= WW-2) {
                int d = 2*WW - 2 - pj - C;
                if (d >= -3 && d <= 3) wcol += GW[d+3];
            }
            float pv = P[R*WW + C];
            float lg = fmaxf(logf(pv), -100.f);
            float l1 = fmaxf(log1pf(-pv), -100.f);
            acc += (double)((wrow * wcol) * (l1 - lg));
        }
    }
    __shared__ double wsum[8];
    int wid = threadIdx.x >> 5;
    for (int off = 16; off; off >>= 1) acc += __shfl_down_sync(0xffffffffu, acc, off);
    if (lane == 0) wsum[wid] = acc;
    __syncthreads();
    if (threadIdx.x == 0) {
        double s2 = 0;
        for (int k = 0; k < (int)(blockDim.x >> 5); k++) s2 += wsum[k];
        atomicAdd(&g_accS, s2);
    }
}

// =====================================================================
// Kernel 5: final reduce — 1024 threads, shuffle tree
// =====================================================================
__global__ void __launch_bounds__(1024) k_fin(float* __restrict__ out) {
    double a = 0, r = 0;
#pragma unroll
    for (int k = 0; k < 4; k++) {
        int i = threadIdx.x + k * 1024;
        a += g_pA[i]; r += g_pB[i];
    }
    int lane = threadIdx.x & 31, wid = threadIdx.x >> 5;
    for (int off = 16; off; off >>= 1) {
        a += __shfl_down_sync(0xffffffffu, a, off);
        r += __shfl_down_sync(0xffffffffu, r, off);
    }
    __shared__ double sa[32], sr[32];
    if (lane == 0) { sa[wid] = a; sr[wid] = r; }
    __syncthreads();
    if (wid == 0) {
        a = sa[lane]; r = sr[lane];
        for (int off = 16; off; off >>= 1) {
            a += __shfl_down_sync(0xffffffffu, a, off);
            r += __shfl_down_sync(0xffffffffu, r, off);
        }
        if (lane == 0)
            out[0] = (float)(((a + g_accS) + 10.0 * r) / (double)NTOT);
    }
}

// ---------------- streams/events for fork-join overlap ----------------
struct HxStreams {
    cudaStream_t side;
    cudaEvent_t evFork, evJoin;
    HxStreams() {
        cudaStreamCreateWithFlags(&side, cudaStreamNonBlocking);
        cudaEventCreateWithFlags(&evFork, cudaEventDisableTiming);
        cudaEventCreateWithFlags(&evJoin, cudaEventDisableTiming);
    }
};
static HxStreams g_hx;

// =====================================================================
extern "C" void kernel_launch(void* const* d_in, const int* in_sizes, int n_in,
                              void* d_out, int out_size) {
    const float* scores = (const float*)d_in[0];
    const float* imgs   = (const float*)d_in[1];
    if (n_in >= 2 && in_sizes[0] > in_sizes[1]) {
        scores = (const float*)d_in[1];
        imgs   = (const float*)d_in[0];
    }
    float* out = (float*)d_out;

    // fork: dense pass runs concurrently with gftt->topk->sparse chain
    cudaEventRecord(g_hx.evFork, 0);
    cudaStreamWaitEvent(g_hx.side, g_hx.evFork, 0);
    k_dense<<<dim3(16, 16, BB), dim3(32, 32), 0, g_hx.side>>>(scores);
    cudaEventRecord(g_hx.evJoin, g_hx.side);

    k_gftt<<<dim3(16, 16, BB), 256>>>(imgs);
    k_topk<<<BB, 512>>>();
    k_sparse<<<dim3(32, BB), 256>>>(scores);

    // join
    cudaStreamWaitEvent(0, g_hx.evJoin, 0);
    k_fin<<<1, 1024>>>(out);
    (void)out_size;
}

// round 15
// speedup vs baseline: 1.2627x; 1.0010x over previous
#include <cuda_runtime.h>
#include <math.h>

#define BB 16
#define HH 512
#define WW 512
#define HWL (HH*WW)
#define NTOT (BB*HWL)
#define NCAND 4096
#define NTOP 500
#define NTILE 4096   // 16 imgs * 16*16 dense tiles

// ------------- device scratch (no allocations) -------------
__device__ float  g_cval[BB*NCAND];
__device__ int    g_cidx[BB*NCAND];
__device__ int    g_pts[BB*NTOP];
__device__ int    g_npt[BB];
__device__ double g_pA[NTILE];
__device__ double g_pB[NTILE];
__device__ double g_accS;

// gaussian(7, sigma=1) weights as literals (FFMA-imm)
#define W0 0.004433048f
#define W1 0.054005582f
#define W2 0.242036223f
#define W3 0.399050277f

__constant__ float GW[7] = {W0, W1, W2, W3, W2, W1, W0};

__device__ __forceinline__ int refl(int t, int n) {   // reflect101
    if (t < 0) t = -t;
    if (t >= n) t = 2 * n - 2 - t;
    return t;
}

// =====================================================================
// Kernel 1: fused gray->sobel->gauss7(structure tensor)->GFTT->NMS->
//           per-8x8-block argmax.  32x32 tile, 256 threads.
// smem overlays (floats), total 8064 = 31.5 KB:
//   D0=0(1764) D1=1764(1764)            [42x42 dx, dy]
//   GR=3528(1936)                        [44x44] (dead after sobel)
//   B0=3528 B1=5040 B2=6552 ..8064      [42x36] (overlay GR)
//   SS=0(1296)                           [36x36] (overlay D0; D dead)
//   RM=1296(1152)                        [36x32] (overlay D)
// blurH: register-blocked 3-col segments (6 LDS/px)
// blurV: register-blocked column sweep (9 LDS/px)
// =====================================================================
__global__ void __launch_bounds__(256) k_gftt(const float* __restrict__ imgs) {
    __shared__ float sm[8064];
    float* D0 = sm;
    float* D1 = sm + 1764;
    float* GR = sm + 3528;
    float* B0 = sm + 3528;
    float* B1 = sm + 5040;
    float* B2 = sm + 6552;
    float* SS = sm;
    float* RM = sm + 1296;

    int b  = blockIdx.z;
    int i0 = blockIdx.y * 32, j0 = blockIdx.x * 32;
    int t  = threadIdx.x;
    int tx = t & 31, tw = t >> 5;
    if (b == 0 && blockIdx.x == 0 && blockIdx.y == 0 && t == 0) g_accS = 0.0;

    const float* img = imgs + (size_t)b * 3 * HWL;

    // --- gray: 44 x 44 (clamped coords) ---
    for (int r = tw; r < 44; r += 8) {
        int gi = min(max(i0 - 6 + r, 0), HH - 1);
        {
            int c = tx;
            int gj = min(max(j0 - 6 + c, 0), WW - 1);
            int p = gi * WW + gj;
            GR[r*44 + c] = 0.299f*img[p] + 0.587f*img[HWL+p] + 0.114f*img[2*HWL+p];
        }
        if (tx < 12) {
            int c = tx + 32;
            int gj = min(max(j0 - 6 + c, 0), WW - 1);
            int p = gi * WW + gj;
            GR[r*44 + c] = 0.299f*img[p] + 0.587f*img[HWL+p] + 0.114f*img[2*HWL+p];
        }
    }
    __syncthreads();

    // --- sobel dx,dy: 42 x 42 at reflected coords ---
    for (int r = tw; r < 42; r += 8) {
        int rg = refl(i0 - 5 + r, HH);
        int rm_ = max(rg - 1, 0) - (i0 - 6);
        int r0_ = rg - (i0 - 6);
        int rp_ = min(rg + 1, HH - 1) - (i0 - 6);
#pragma unroll
        for (int m = 0; m < 2; m++) {
            int c = tx + 32 * m;
            if (c < 42) {
                int cg = refl(j0 - 5 + c, WW);
                int cm_ = max(cg - 1, 0) - (j0 - 6);
                int c0_ = cg - (j0 - 6);
                int cp_ = min(cg + 1, WW - 1) - (j0 - 6);
                float A = GR[rm_*44+cm_], Bv = GR[rm_*44+c0_], C = GR[rm_*44+cp_];
                float D = GR[r0_*44+cm_],                      F = GR[r0_*44+cp_];
                float G = GR[rp_*44+cm_], H  = GR[rp_*44+c0_], K = GR[rp_*44+cp_];
                int o = r * 42 + c;
                D0[o] = (C - A + 2.f*(F - D) + K - G) * 0.125f;
                D1[o] = (G - A + 2.f*(H - Bv) + K - C) * 0.125f;
            }
        }
    }
    __syncthreads();

    // --- horizontal gauss7 on products: register-blocked 3-col segments ---
    // 42 rows x 12 segments = 504 tasks; each loads 9 D0 + 9 D1 once,
    // forms products, emits 3 outputs with symmetric weight folding.
#pragma unroll
    for (int k2 = 0; k2 < 2; k2++) {
        int idx = t + k2 * 256;
        if (idx < 504) {
            int r = idx / 12;
            int seg = idx - r * 12;
            int c0 = seg * 3;
            int base = r * 42 + c0;
            float p0[9], p1[9], p2[9];
#pragma unroll
            for (int q = 0; q < 9; q++) {
                float dx = D0[base + q], dy = D1[base + q];
                p0[q] = dx * dx; p1[q] = dy * dy; p2[q] = dx * dy;
            }
            int o = r * 36 + c0;
#pragma unroll
            for (int rr = 0; rr < 3; rr++) {
                float s0 = W0*(p0[rr]+p0[rr+6]) + W1*(p0[rr+1]+p0[rr+5])
                         + W2*(p0[rr+2]+p0[rr+4]) + W3*p0[rr+3];
                float s1 = W0*(p1[rr]+p1[rr+6]) + W1*(p1[rr+1]+p1[rr+5])
                         + W2*(p1[rr+2]+p1[rr+4]) + W3*p1[rr+3];
                float s2 = W0*(p2[rr]+p2[rr+6]) + W1*(p2[rr+1]+p2[rr+5])
                         + W2*(p2[rr+2]+p2[rr+4]) + W3*p2[rr+3];
                B0[o + rr] = s0; B1[o + rr] = s1; B2[o + rr] = s2;
            }
        }
    }
    __syncthreads();

    // --- vertical gauss7 + GFTT response: 36 x 36 ---
    // register-blocked column sweep: 12 segs x 36 cols = 432 tasks,
    // each task: 3 output rows in one column; 9 input rows loaded once.
#pragma unroll
    for (int k2 = 0; k2 < 2; k2++) {
        int idx = t + k2 * 256;
        if (idx < 432) {
            int seg = idx / 36;
            int c = idx - seg * 36;
            int r0 = seg * 3;
            float v0[9], v1[9], v2[9];
#pragma unroll
            for (int q = 0; q < 9; q++) {
                int row = (r0 + q) * 36 + c;
                v0[q] = B0[row]; v1[q] = B1[row]; v2[q] = B2[row];
            }
#pragma unroll
            for (int rr = 0; rr < 3; rr++) {
                float a  = W0*(v0[rr]+v0[rr+6]) + W1*(v0[rr+1]+v0[rr+5])
                         + W2*(v0[rr+2]+v0[rr+4]) + W3*v0[rr+3];
                float cc = W0*(v1[rr]+v1[rr+6]) + W1*(v1[rr+1]+v1[rr+5])
                         + W2*(v1[rr+2]+v1[rr+4]) + W3*v1[rr+3];
                float e  = W0*(v2[rr]+v2[rr+6]) + W1*(v2[rr+1]+v2[rr+5])
                         + W2*(v2[rr+2]+v2[rr+4]) + W3*v2[rr+3];
                float det = a * cc - e * e, tr = a + cc;
                float s = 0.5f * (tr - sqrtf(fabsf(tr * tr - 4.f * det)));
                int gi = i0 - 2 + r0 + rr, gj = j0 - 2 + c;
                SS[(r0 + rr) * 36 + c] =
                    (gi >= 0 && gi < HH && gj >= 0 && gj < WW) ? s : -INFINITY;
            }
        }
    }
    __syncthreads();

    // --- NMS row-max: 36 x 32 ---
    for (int r = tw; r < 36; r += 8) {
        float mx = SS[r * 36 + tx];
#pragma unroll
        for (int q = 1; q < 5; q++) mx = fmaxf(mx, SS[r * 36 + tx + q]);
        RM[r * 32 + tx] = mx;
    }
    __syncthreads();

    // --- per-pixel NMS + 8x8 block argmax: warp tw handles blocks 2tw, 2tw+1 ---
#pragma unroll
    for (int k = 0; k < 2; k++) {
        int bb = 2 * tw + k;
        int br = bb >> 2, bc = bb & 3;
        float bv = -1.f; int bi = 0x7fffffff;
#pragma unroll
        for (int h = 0; h < 2; h++) {
            int e = tx + 32 * h;
            int r = br * 8 + (e >> 3), c = bc * 8 + (e & 7);
            float s = SS[(r + 2) * 36 + c + 2];
            float mx = RM[r * 32 + c];
#pragma unroll
            for (int q = 1; q < 5; q++) mx = fmaxf(mx, RM[(r + q) * 32 + c]);
            float v = (s == mx) ? s : 0.f;
            int gix = (i0 + r) * WW + (j0 + c);
            if (v > bv || (v == bv && gix < bi)) { bv = v; bi = gix; }
        }
#pragma unroll
        for (int off = 16; off >= 1; off >>= 1) {
            float ov = __shfl_down_sync(0xffffffffu, bv, off);
            int   oi = __shfl_down_sync(0xffffffffu, bi, off);
            if (ov > bv || (ov == bv && oi < bi)) { bv = ov; bi = oi; }
        }
        if (tx == 0) {
            int cy = blockIdx.y * 4 + br;
            int cx = blockIdx.x * 4 + bc;
            g_cval[b * NCAND + cy * 64 + cx] = bv;
            g_cidx[b * NCAND + cy * 64 + cx] = bi;
        }
    }
}

// =====================================================================
// Kernel 2: per-image top-500 via 4-round radix select, parallel scan
// =====================================================================
__global__ void __launch_bounds__(512) k_topk() {
    int b = blockIdx.x;
    const float* cv = g_cval + b * NCAND;
    const int*   ci = g_cidx + b * NCAND;
    __shared__ unsigned hist[256];
    __shared__ unsigned scan[256];
    __shared__ unsigned sh_prefix, sh_k, sh_cnt, sh_eqcnt;
    __shared__ int eqidx[256];

    unsigned u[8];
#pragma unroll
    for (int i = 0; i < 8; i++) {
        unsigned bits = __float_as_uint(cv[threadIdx.x + i * 512]);
        u[i] = bits ^ ((bits & 0x80000000u) ? 0xFFFFFFFFu : 0x80000000u);
    }
    if (threadIdx.x == 0) { sh_prefix = 0; sh_k = NTOP; sh_cnt = 0; sh_eqcnt = 0; }

    for (int shift = 24; shift >= 0; shift -= 8) {
        if (threadIdx.x < 256) hist[threadIdx.x] = 0;
        __syncthreads();
        unsigned pre = sh_prefix;
#pragma unroll
        for (int i = 0; i < 8; i++) {
            if (((unsigned long long)u[i] >> (shift + 8)) == (unsigned long long)pre)
                atomicAdd(&hist[(u[i] >> shift) & 255u], 1u);
        }
        __syncthreads();
        if (threadIdx.x < 256) scan[threadIdx.x] = hist[threadIdx.x];
        __syncthreads();
        for (int off = 1; off < 256; off <<= 1) {
            unsigned add = 0;
            if (threadIdx.x < 256 && threadIdx.x + off < 256)
                add = scan[threadIdx.x + off];
            __syncthreads();
            if (threadIdx.x < 256) scan[threadIdx.x] += add;
            __syncthreads();
        }
        if (threadIdx.x < 256) {
            unsigned k = sh_k;
            unsigned Sq  = scan[threadIdx.x];
            unsigned Sq1 = (threadIdx.x == 255) ? 0u : scan[threadIdx.x + 1];
            if (Sq >= k && Sq1 < k) {
                sh_k = k - Sq1;
                sh_prefix = (pre << 8) | (unsigned)threadIdx.x;
            }
        }
        __syncthreads();
    }

    unsigned uth = sh_prefix;
    int kneed = (int)sh_k;
    float thresh = (uth & 0x80000000u) ? __uint_as_float(uth ^ 0x80000000u)
                                       : __uint_as_float(~uth);

    if (thresh > 0.f) {
#pragma unroll
        for (int i = 0; i < 8; i++) {
            int idx = threadIdx.x + i * 512;
            if (u[i] > uth) {
                unsigned p = atomicAdd(&sh_cnt, 1u);
                if (p < NTOP) g_pts[b * NTOP + p] = ci[idx];
            } else if (u[i] == uth) {
                unsigned p = atomicAdd(&sh_eqcnt, 1u);
                if (p < 256) eqidx[p] = ci[idx];
            }
        }
        __syncthreads();
        if (threadIdx.x == 0) {
            int base = min((int)sh_cnt, NTOP);
            int nn = min((int)sh_eqcnt, 256);
            int added = 0;
            while (added < kneed && added < nn) {
                int best = -1, bi2 = 0x7fffffff;
                for (int q = 0; q < nn; q++)
                    if (eqidx[q] >= 0 && eqidx[q] < bi2) { bi2 = eqidx[q]; best = q; }
                if (best < 0) break;
                if (base + added < NTOP) g_pts[b * NTOP + base + added] = bi2;
                eqidx[best] = -1;
                added++;
            }
            g_npt[b] = min(base + added, NTOP);
        }
    } else {
#pragma unroll
        for (int i = 0; i < 8; i++) {
            int idx = threadIdx.x + i * 512;
            if (u[i] > 0x80000000u) {               // ordered form of +0.0
                unsigned p = atomicAdd(&sh_cnt, 1u);
                if (p < NTOP) g_pts[b * NTOP + p] = ci[idx];
            }
        }
        __syncthreads();
        if (threadIdx.x == 0) g_npt[b] = min((int)sh_cnt, NTOP);
    }
}

// =====================================================================
// Kernel 3: dense part — sum(-log1mp) and reg = p*exp(-lap), tiled 32x32
// =====================================================================
__global__ void __launch_bounds__(1024) k_dense(const float* __restrict__ sc) {
    __shared__ float s[36*36];
    __shared__ float h[36*32];
    __shared__ double w1[32], w2[32];
    int b = blockIdx.z, i0 = blockIdx.y * 32, j0 = blockIdx.x * 32;
    int tx = threadIdx.x, ty = threadIdx.y, t = ty*32 + tx;
    const float* P = sc + (size_t)b * HWL;
    for (int idx = t; idx < 36*36; idx += 1024) {
        int a = idx / 36, c = idx % 36;
        s[idx] = P[refl(i0 - 2 + a, HH) * WW + refl(j0 - 2 + c, WW)];
    }
    __syncthreads();
    for (int idx = t; idx < 36*32; idx += 1024) {
        int r = idx / 32, c = idx % 32;
        float x = s[r*36 + c];
#pragma unroll
        for (int k = 1; k < 5; k++) x += s[r*36 + c + k];
        h[idx] = x;
    }
    __syncthreads();
    float p = s[(ty+2)*36 + tx + 2];
    float box = h[ty*32 + tx];
#pragma unroll
    for (int k = 1; k < 5; k++) box += h[(ty+k)*32 + tx];
    float lap = (box - 25.f * p) * (1.f / 48.f);
    double reg = (double)(p * expf(-lap));
    double bce = (double)(-fmaxf(log1pf(-p), -100.f));
    for (int off = 16; off; off >>= 1) {
        bce += __shfl_down_sync(0xffffffffu, bce, off);
        reg += __shfl_down_sync(0xffffffffu, reg, off);
    }
    if ((t & 31) == 0) { w1[t >> 5] = bce; w2[t >> 5] = reg; }
    __syncthreads();
    if (t < 32) {
        bce = w1[t]; reg = w2[t];
        for (int off = 16; off; off >>= 1) {
            bce += __shfl_down_sync(0xffffffffu, bce, off);
            reg += __shfl_down_sync(0xffffffffu, reg, off);
        }
        if (t == 0) {
            int tile = (b * 16 + blockIdx.y) * 16 + blockIdx.x;
            g_pA[tile] = bce; g_pB[tile] = reg;
        }
    }
}

// =====================================================================
// Kernel 4: sparse corner-BCE, warp-per-point (lanes cover 49 taps)
// =====================================================================
__global__ void k_sparse(const float* __restrict__ sc) {
    int b = blockIdx.y;
    int n = g_npt[b];
    const float* P = sc + (size_t)b * HWL;
    int warpsPerImg = gridDim.x * (blockDim.x >> 5);
    int gw = blockIdx.x * (blockDim.x >> 5) + (threadIdx.x >> 5);
    int lane = threadIdx.x & 31;
    double acc = 0.0;
    for (int q = gw; q < n; q += warpsPerImg) {
        int pix = g_pts[b*NTOP + q];
        int pi = pix >> 9, pj = pix & 511;
#pragma unroll
        for (int half = 0; half < 2; half++) {
            int tap = lane + 32 * half;
            if (tap >= 49) break;
            int kr = tap / 7, kc = tap - kr * 7;
            int R = pi - 3 + kr, C = pj - 3 + kc;
            if (R < 0 || R >= HH || C < 0 || C >= WW) continue;
            float wrow = GW[kr];
            if (pi >= 1 && pi <= 3) {
                int d = -pi - R;
                if (d >= -3 && d <= 3) wrow += GW[d+3];
            }
            if (pi >= HH-4 && pi <= HH-2) {
                int d = 2*HH - 2 - pi - R;
                if (d >= -3 && d <= 3) wrow += GW[d+3];
            }
            float wcol = GW[kc];
            if (pj >= 1 && pj <= 3) {
                int d = -pj - C;
                if (d >= -3 && d <= 3) wcol += GW[d+3];
            }
            if (pj >= WW-4 && pj <= WW-2) {
                int d = 2*WW - 2 - pj - C;
                if (d >= -3 && d <= 3) wcol += GW[d+3];
            }
            float pv = P[R*WW + C];
            float lg = fmaxf(logf(pv), -100.f);
            float l1 = fmaxf(log1pf(-pv), -100.f);
            acc += (double)((wrow * wcol) * (l1 - lg));
        }
    }
    __shared__ double wsum[8];
    int wid = threadIdx.x >> 5;
    for (int off = 16; off; off >>= 1) acc += __shfl_down_sync(0xffffffffu, acc, off);
    if (lane == 0) wsum[wid] = acc;
    __syncthreads();
    if (threadIdx.x == 0) {
        double s2 = 0;
        for (int k = 0; k < (int)(blockDim.x >> 5); k++) s2 += wsum[k];
        atomicAdd(&g_accS, s2);
    }
}

// =====================================================================
// Kernel 5: final reduce — 1024 threads, shuffle tree
// =====================================================================
__global__ void __launch_bounds__(1024) k_fin(float* __restrict__ out) {
    double a = 0, r = 0;
#pragma unroll
    for (int k = 0; k < 4; k++) {
        int i = threadIdx.x + k * 1024;
        a += g_pA[i]; r += g_pB[i];
    }
    int lane = threadIdx.x & 31, wid = threadIdx.x >> 5;
    for (int off = 16; off; off >>= 1) {
        a += __shfl_down_sync(0xffffffffu, a, off);
        r += __shfl_down_sync(0xffffffffu, r, off);
    }
    __shared__ double sa[32], sr[32];
    if (lane == 0) { sa[wid] = a; sr[wid] = r; }
    __syncthreads();
    if (wid == 0) {
        a = sa[lane]; r = sr[lane];
        for (int off = 16; off; off >>= 1) {
            a += __shfl_down_sync(0xffffffffu, a, off);
            r += __shfl_down_sync(0xffffffffu, r, off);
        }
        if (lane == 0)
            out[0] = (float)(((a + g_accS) + 10.0 * r) / (double)NTOT);
    }
}

// ---------------- streams/events for fork-join overlap ----------------
struct HxStreams {
    cudaStream_t side;
    cudaEvent_t evFork, evJoin;
    HxStreams() {
        cudaStreamCreateWithFlags(&side, cudaStreamNonBlocking);
        cudaEventCreateWithFlags(&evFork, cudaEventDisableTiming);
        cudaEventCreateWithFlags(&evJoin, cudaEventDisableTiming);
    }
};
static HxStreams g_hx;

// =====================================================================
extern "C" void kernel_launch(void* const* d_in, const int* in_sizes, int n_in,
                              void* d_out, int out_size) {
    const float* scores = (const float*)d_in[0];
    const float* imgs   = (const float*)d_in[1];
    if (n_in >= 2 && in_sizes[0] > in_sizes[1]) {
        scores = (const float*)d_in[1];
        imgs   = (const float*)d_in[0];
    }
    float* out = (float*)d_out;

    // fork: dense pass runs concurrently with gftt->topk->sparse chain
    cudaEventRecord(g_hx.evFork, 0);
    cudaStreamWaitEvent(g_hx.side, g_hx.evFork, 0);
    k_dense<<<dim3(16, 16, BB), dim3(32, 32), 0, g_hx.side>>>(scores);
    cudaEventRecord(g_hx.evJoin, g_hx.side);

    k_gftt<<<dim3(16, 16, BB), 256>>>(imgs);
    k_topk<<<BB, 512>>>();
    k_sparse<<<dim3(32, BB), 256>>>(scores);

    // join
    cudaStreamWaitEvent(0, g_hx.evJoin, 0);
    k_fin<<<1, 1024>>>(out);
    (void)out_size;
}